// round 1
// baseline (speedup 1.0000x reference)
#include <cuda_runtime.h>

#define BB 2
#define SS 1024
#define DD 1024
#define HH 16
#define DKK 64
#define FF_ 4096
#define LL 6

// ---------------- scratch (__device__ globals: allocation-free) --------------
__device__ float g_x [BB*SS*DD];
__device__ float g_h [BB*SS*DD];
__device__ float g_q [BB*SS*DD];
__device__ float g_k [BB*SS*DD];
__device__ float g_v [BB*SS*DD];
__device__ float g_ao[BB*SS*DD];
__device__ float g_ff[BB*SS*FF_];
__device__ float g_sc[BB*HH*SS*SS];   // 128 MB attention scores scratch

// ---------------- block reductions -------------------------------------------
__device__ __forceinline__ float blockReduceSum(float v) {
    __shared__ float sh[8];
    __shared__ float res;
    int lane = threadIdx.x & 31, w = threadIdx.x >> 5;
#pragma unroll
    for (int o = 16; o; o >>= 1) v += __shfl_xor_sync(0xffffffffu, v, o);
    __syncthreads();
    if (lane == 0) sh[w] = v;
    __syncthreads();
    if (threadIdx.x == 0) {
        float s = 0.f;
#pragma unroll
        for (int i = 0; i < 8; i++) s += sh[i];
        res = s;
    }
    __syncthreads();
    return res;
}

__device__ __forceinline__ float blockReduceMax(float v) {
    __shared__ float sh[8];
    __shared__ float res;
    int lane = threadIdx.x & 31, w = threadIdx.x >> 5;
#pragma unroll
    for (int o = 16; o; o >>= 1) v = fmaxf(v, __shfl_xor_sync(0xffffffffu, v, o));
    __syncthreads();
    if (lane == 0) sh[w] = v;
    __syncthreads();
    if (threadIdx.x == 0) {
        float s = sh[0];
#pragma unroll
        for (int i = 1; i < 8; i++) s = fmaxf(s, sh[i]);
        res = s;
    }
    __syncthreads();
    return res;
}

// ---------------- embed: x = emb[ids]*sqrt(D) + pe ---------------------------
__global__ void __launch_bounds__(256) embed_kernel(
    const int* __restrict__ ids, const float* __restrict__ emb,
    const float* __restrict__ pe, float* __restrict__ x)
{
    int row = blockIdx.x;            // 0..B*S-1
    int col = threadIdx.x * 4;       // D = 1024 = 256*4
    int id  = ids[row];
    int s   = row & (SS - 1);
    float4 e = *(const float4*)&emb[(size_t)id * DD + col];
    float4 p = *(const float4*)&pe [(size_t)s  * DD + col];
    float4 o;
    o.x = e.x * 32.0f + p.x;
    o.y = e.y * 32.0f + p.y;
    o.z = e.z * 32.0f + p.z;
    o.w = e.w * 32.0f + p.w;
    *(float4*)&x[(size_t)row * DD + col] = o;
}

// ---------------- LayerNorm (one block per row) -------------------------------
__global__ void __launch_bounds__(256) ln_kernel(
    const float* __restrict__ x, const float* __restrict__ g,
    const float* __restrict__ b, float* __restrict__ out)
{
    int row = blockIdx.x;
    int col = threadIdx.x * 4;
    float4 v = *(const float4*)&x[(size_t)row * DD + col];
    float mean = blockReduceSum(v.x + v.y + v.z + v.w) * (1.0f / DD);
    float dx = v.x - mean, dy = v.y - mean, dz = v.z - mean, dw = v.w - mean;
    float var = blockReduceSum(dx*dx + dy*dy + dz*dz + dw*dw) * (1.0f / DD);
    float rstd = rsqrtf(var + 1e-6f);
    float4 gg = *(const float4*)&g[col];
    float4 bb = *(const float4*)&b[col];
    float4 o;
    o.x = dx * rstd * gg.x + bb.x;
    o.y = dy * rstd * gg.y + bb.y;
    o.z = dz * rstd * gg.z + bb.z;
    o.w = dw * rstd * gg.w + bb.w;
    *(float4*)&out[(size_t)row * DD + col] = o;
}

// ---------------- masked softmax over last dim (S=1024) -----------------------
__global__ void __launch_bounds__(256) softmax_kernel(
    float* __restrict__ sc, const float* __restrict__ am)
{
    size_t row = blockIdx.x;                // 0..B*H*S-1
    int b = blockIdx.x / (HH * SS);
    float* p = sc + row * SS;
    int col = threadIdx.x * 4;
    float4 v = *(float4*)&p[col];
    float4 m = *(const float4*)&am[(size_t)b * SS + col];
    v.x = (m.x == 0.f) ? -1e9f : v.x;
    v.y = (m.y == 0.f) ? -1e9f : v.y;
    v.z = (m.z == 0.f) ? -1e9f : v.z;
    v.w = (m.w == 0.f) ? -1e9f : v.w;
    float mx = blockReduceMax(fmaxf(fmaxf(v.x, v.y), fmaxf(v.z, v.w)));
    v.x = expf(v.x - mx);
    v.y = expf(v.y - mx);
    v.z = expf(v.z - mx);
    v.w = expf(v.w - mx);
    float s = blockReduceSum(v.x + v.y + v.z + v.w);
    float inv = 1.0f / s;
    v.x *= inv; v.y *= inv; v.z *= inv; v.w *= inv;
    *(float4*)&p[col] = v;
}

// ---------------- scores = Q @ K^T / 8 (per b,h; K=DK=64) --------------------
__global__ void __launch_bounds__(256) scores_kernel(
    const float* __restrict__ q, const float* __restrict__ kp,
    float* __restrict__ sc)
{
    int z = blockIdx.z;                          // b*H + h
    size_t off = (size_t)(z / HH) * SS * DD + (size_t)(z % HH) * DKK;
    const float* Q  = q  + off;
    const float* Kt = kp + off;
    float* Sc = sc + (size_t)z * SS * SS;
    int bi = blockIdx.y * 64, bj = blockIdx.x * 64;
    __shared__ float Qs[16][64];
    __shared__ float Ks[16][64];
    int tid = threadIdx.x, tx = tid & 15, ty = tid >> 4;
    int lr = tid >> 2, lk = (tid & 3) * 4;
    float acc[4][4] = {};
#pragma unroll
    for (int k0 = 0; k0 < DKK; k0 += 16) {
        float4 rq = *(const float4*)&Q [(size_t)(bi + lr) * DD + k0 + lk];
        float4 rk = *(const float4*)&Kt[(size_t)(bj + lr) * DD + k0 + lk];
        __syncthreads();
        Qs[lk+0][lr] = rq.x; Qs[lk+1][lr] = rq.y; Qs[lk+2][lr] = rq.z; Qs[lk+3][lr] = rq.w;
        Ks[lk+0][lr] = rk.x; Ks[lk+1][lr] = rk.y; Ks[lk+2][lr] = rk.z; Ks[lk+3][lr] = rk.w;
        __syncthreads();
#pragma unroll
        for (int kk = 0; kk < 16; kk++) {
            float4 a = *(float4*)&Qs[kk][ty * 4];
            float4 b = *(float4*)&Ks[kk][tx * 4];
            acc[0][0] += a.x*b.x; acc[0][1] += a.x*b.y; acc[0][2] += a.x*b.z; acc[0][3] += a.x*b.w;
            acc[1][0] += a.y*b.x; acc[1][1] += a.y*b.y; acc[1][2] += a.y*b.z; acc[1][3] += a.y*b.w;
            acc[2][0] += a.z*b.x; acc[2][1] += a.z*b.y; acc[2][2] += a.z*b.z; acc[2][3] += a.z*b.w;
            acc[3][0] += a.w*b.x; acc[3][1] += a.w*b.y; acc[3][2] += a.w*b.z; acc[3][3] += a.w*b.w;
        }
    }
#pragma unroll
    for (int u = 0; u < 4; u++) {
        float4 o;
        o.x = acc[u][0] * 0.125f;
        o.y = acc[u][1] * 0.125f;
        o.z = acc[u][2] * 0.125f;
        o.w = acc[u][3] * 0.125f;
        *(float4*)&Sc[(size_t)(bi + ty*4 + u) * SS + bj + tx*4] = o;
    }
}

// ---------------- generic SGEMM: 128x128x8 tiles, 8x8 microtile, dbl-buffered -
// EP: 0=none  1=+bias  2=relu(+bias)  3=+bias+residual
// ATTN: blockIdx.z -> per-(b,h) offsets for P@V
template<int EP, bool ATTN>
__global__ void __launch_bounds__(256) sgemm(
    const float* __restrict__ A, const float* __restrict__ Bm,
    const float* __restrict__ bias, const float* __restrict__ Rs,
    float* __restrict__ C,
    int M, int N, int K, int lda, int ldb, int ldc)
{
    if (ATTN) {
        int z = blockIdx.z;
        A += (size_t)z * (size_t)SS * SS;
        size_t off = (size_t)(z / HH) * SS * DD + (size_t)(z % HH) * DKK;
        Bm += off; C += off;
    }
    __shared__ float As[8][128];
    __shared__ float Bs[8][128];
    int tid = threadIdx.x;
    int tx = tid & 15, ty = tid >> 4;
    int bm = blockIdx.y * 128, bn = blockIdx.x * 128;
    int arow = tid >> 1,  ak   = (tid & 1) * 4;
    int brow = tid >> 5,  bcol = (tid & 31) * 4;
    const float* Aptr = A  + (size_t)(bm + arow) * lda + ak;
    const float* Bptr = Bm + (size_t)brow * ldb + bn + bcol;
    bool bok = (bn + bcol) < N;

    float acc[8][8] = {};
    int kt = K >> 3;

    float4 ra = *(const float4*)Aptr;
    float4 rb = bok ? *(const float4*)Bptr : make_float4(0.f, 0.f, 0.f, 0.f);
    As[ak+0][arow] = ra.x; As[ak+1][arow] = ra.y; As[ak+2][arow] = ra.z; As[ak+3][arow] = ra.w;
    *(float4*)&Bs[brow][bcol] = rb;
    __syncthreads();

    for (int t = 0; t < kt; t++) {
        float4 na, nb;
        if (t + 1 < kt) {
            na = *(const float4*)(Aptr + (t + 1) * 8);
            nb = bok ? *(const float4*)(Bptr + (size_t)(t + 1) * 8 * ldb)
                     : make_float4(0.f, 0.f, 0.f, 0.f);
        }
#pragma unroll
        for (int kk = 0; kk < 8; kk++) {
            float4 a0 = *(float4*)&As[kk][ty * 4];
            float4 a1 = *(float4*)&As[kk][ty * 4 + 64];
            float4 b0 = *(float4*)&Bs[kk][tx * 4];
            float4 b1 = *(float4*)&Bs[kk][tx * 4 + 64];
            float av[8] = {a0.x, a0.y, a0.z, a0.w, a1.x, a1.y, a1.z, a1.w};
            float bv[8] = {b0.x, b0.y, b0.z, b0.w, b1.x, b1.y, b1.z, b1.w};
#pragma unroll
            for (int i = 0; i < 8; i++)
#pragma unroll
                for (int j = 0; j < 8; j++)
                    acc[i][j] += av[i] * bv[j];
        }
        if (t + 1 < kt) {
            __syncthreads();
            As[ak+0][arow] = na.x; As[ak+1][arow] = na.y;
            As[ak+2][arow] = na.z; As[ak+3][arow] = na.w;
            *(float4*)&Bs[brow][bcol] = nb;
            __syncthreads();
        }
    }

#pragma unroll
    for (int ih = 0; ih < 2; ih++)
#pragma unroll
    for (int u = 0; u < 4; u++) {
        int r = bm + ih * 64 + ty * 4 + u;     // M always multiple of 128 here
#pragma unroll
        for (int jh = 0; jh < 2; jh++) {
            int c = bn + jh * 64 + tx * 4;
            if (c >= N) continue;
            float4 o;
            o.x = acc[ih*4 + u][jh*4 + 0];
            o.y = acc[ih*4 + u][jh*4 + 1];
            o.z = acc[ih*4 + u][jh*4 + 2];
            o.w = acc[ih*4 + u][jh*4 + 3];
            if (EP >= 1) {
                float4 bi = *(const float4*)&bias[c];
                o.x += bi.x; o.y += bi.y; o.z += bi.z; o.w += bi.w;
            }
            if (EP == 2) {
                o.x = fmaxf(o.x, 0.f); o.y = fmaxf(o.y, 0.f);
                o.z = fmaxf(o.z, 0.f); o.w = fmaxf(o.w, 0.f);
            }
            if (EP == 3) {
                float4 rr = *(const float4*)&Rs[(size_t)r * ldc + c];
                o.x += rr.x; o.y += rr.y; o.z += rr.z; o.w += rr.w;
            }
            *(float4*)&C[(size_t)r * ldc + c] = o;
        }
    }
}

// ---------------- host orchestration ------------------------------------------
extern "C" void kernel_launch(void* const* d_in, const int* in_sizes, int n_in,
                              void* d_out, int out_size)
{
    const int*   ids  = (const int*)  d_in[0];
    const float* am   = (const float*)d_in[1];
    const float* emb  = (const float*)d_in[2];
    const float* pe   = (const float*)d_in[3];
    const float* wq   = (const float*)d_in[4];
    const float* wk   = (const float*)d_in[5];
    const float* wv   = (const float*)d_in[6];
    const float* wo   = (const float*)d_in[7];
    const float* bo   = (const float*)d_in[8];
    const float* w1   = (const float*)d_in[9];
    const float* b1   = (const float*)d_in[10];
    const float* w2   = (const float*)d_in[11];
    const float* b2   = (const float*)d_in[12];
    const float* ln1s = (const float*)d_in[13];
    const float* ln1b = (const float*)d_in[14];
    const float* ln2s = (const float*)d_in[15];
    const float* ln2b = (const float*)d_in[16];
    const float* lnfs = (const float*)d_in[17];
    const float* lnfb = (const float*)d_in[18];
    float* out = (float*)d_out;

    float *x, *h, *q, *k, *v, *ao, *ff, *sc;
    cudaGetSymbolAddress((void**)&x,  g_x);
    cudaGetSymbolAddress((void**)&h,  g_h);
    cudaGetSymbolAddress((void**)&q,  g_q);
    cudaGetSymbolAddress((void**)&k,  g_k);
    cudaGetSymbolAddress((void**)&v,  g_v);
    cudaGetSymbolAddress((void**)&ao, g_ao);
    cudaGetSymbolAddress((void**)&ff, g_ff);
    cudaGetSymbolAddress((void**)&sc, g_sc);

    const int M = BB * SS;   // 2048 rows

    embed_kernel<<<M, 256>>>(ids, emb, pe, x);

    for (int l = 0; l < LL; l++) {
        const float* Wq = wq + (size_t)l * DD * DD;
        const float* Wk = wk + (size_t)l * DD * DD;
        const float* Wv = wv + (size_t)l * DD * DD;
        const float* Wo = wo + (size_t)l * DD * DD;
        const float* W1 = w1 + (size_t)l * DD * FF_;
        const float* W2 = w2 + (size_t)l * FF_ * DD;

        // LN1
        ln_kernel<<<M, 256>>>(x, ln1s + l*DD, ln1b + l*DD, h);

        // Q, K, V projections
        dim3 gp(DD / 128, M / 128, 1);
        sgemm<0, false><<<gp, 256>>>(h, Wq, nullptr, nullptr, q, M, DD, DD, DD, DD, DD);
        sgemm<0, false><<<gp, 256>>>(h, Wk, nullptr, nullptr, k, M, DD, DD, DD, DD, DD);
        sgemm<0, false><<<gp, 256>>>(h, Wv, nullptr, nullptr, v, M, DD, DD, DD, DD, DD);

        // scores = QK^T / sqrt(dk)
        scores_kernel<<<dim3(SS/64, SS/64, BB*HH), 256>>>(q, k, sc);

        // masked softmax
        softmax_kernel<<<BB*HH*SS, 256>>>(sc, am);

        // attn_out = P @ V  (per b,h)
        sgemm<0, true><<<dim3(1, SS/128, BB*HH), 256>>>(sc, v, nullptr, nullptr, ao,
                                                        SS, DKK, SS, SS, DD, DD);

        // x = x + attn_out @ Wo + bo
        sgemm<3, false><<<dim3(DD/128, M/128, 1), 256>>>(ao, Wo, bo + l*DD, x, x,
                                                         M, DD, DD, DD, DD, DD);

        // LN2
        ln_kernel<<<M, 256>>>(x, ln2s + l*DD, ln2b + l*DD, h);

        // ff = relu(h @ W1 + b1)
        sgemm<2, false><<<dim3(FF_/128, M/128, 1), 256>>>(h, W1, b1 + l*FF_, nullptr, ff,
                                                          M, FF_, DD, DD, FF_, FF_);

        // x = x + ff @ W2 + b2
        sgemm<3, false><<<dim3(DD/128, M/128, 1), 256>>>(ff, W2, b2 + l*DD, x, x,
                                                         M, DD, FF_, FF_, DD, DD);
    }

    // final LN -> output
    ln_kernel<<<M, 256>>>(x, lnfs, lnfb, out);
}

// round 3
// speedup vs baseline: 1.9893x; 1.9893x over previous
#include <cuda_runtime.h>
#include <cuda_bf16.h>
#include <cstdint>

#define BB 2
#define SS 1024
#define DD 1024
#define HH 16
#define DKK 64
#define FF_ 4096
#define LL 6

// ---------------- scratch (__device__ globals: allocation-free) --------------
__device__ float g_x [BB*SS*DD];
__device__ float g_h [BB*SS*DD];
__device__ float g_q [BB*SS*DD];
__device__ float g_k [BB*SS*DD];
__device__ float g_v [BB*SS*DD];
__device__ float g_ao[BB*SS*DD];
__device__ float g_ff[BB*SS*FF_];
__device__ float g_sc[BB*HH*SS*SS];   // 128 MB attention scores scratch

// split-precision bf16 buffers
// weights: per layer [Wq Wk Wv Wo W1 W2], each stored TRANSPOSED [N,K]
#define WL_CHUNK (4*DD*DD + DD*FF_ + FF_*DD)
#define W_TOTAL  (LL * WL_CHUNK)
#define OFF_Q 0
#define OFF_K (DD*DD)
#define OFF_V (2*DD*DD)
#define OFF_O (3*DD*DD)
#define OFF_1 (4*DD*DD)
#define OFF_2 (4*DD*DD + DD*FF_)
__device__ __nv_bfloat16 g_wh[W_TOTAL];
__device__ __nv_bfloat16 g_wl[W_TOTAL];
// activations split (max 2048 x 4096)
__device__ __nv_bfloat16 g_ah[BB*SS*FF_];
__device__ __nv_bfloat16 g_al[BB*SS*FF_];

// ---------------- PTX helpers -------------------------------------------------
__device__ __forceinline__ uint32_t smem_u32(const void* p) {
    uint32_t a;
    asm("{ .reg .u64 t; cvta.to.shared.u64 t, %1; cvt.u32.u64 %0, t; }" : "=r"(a) : "l"(p));
    return a;
}
#define CP16(d, s) asm volatile("cp.async.cg.shared.global [%0], [%1], 16;" :: "r"(d), "l"(s))
#define CP_COMMIT() asm volatile("cp.async.commit_group;" ::: "memory")

#define LDSM4(r, addr) \
    asm volatile("ldmatrix.sync.aligned.m8n8.x4.shared.b16 {%0,%1,%2,%3}, [%4];" \
        : "=r"((r)[0]), "=r"((r)[1]), "=r"((r)[2]), "=r"((r)[3]) : "r"(addr))

#define MMA16816(d, a, b) \
    asm volatile("mma.sync.aligned.m16n8k16.row.col.f32.bf16.bf16.f32 " \
        "{%0,%1,%2,%3}, {%4,%5,%6,%7}, {%8,%9}, {%0,%1,%2,%3};" \
        : "+f"((d)[0]), "+f"((d)[1]), "+f"((d)[2]), "+f"((d)[3]) \
        : "r"((a)[0]), "r"((a)[1]), "r"((a)[2]), "r"((a)[3]), "r"((b)[0]), "r"((b)[1]))

// ---------------- block reductions --------------------------------------------
__device__ __forceinline__ float blockReduceSum(float v) {
    __shared__ float sh[8];
    __shared__ float res;
    int lane = threadIdx.x & 31, w = threadIdx.x >> 5;
#pragma unroll
    for (int o = 16; o; o >>= 1) v += __shfl_xor_sync(0xffffffffu, v, o);
    __syncthreads();
    if (lane == 0) sh[w] = v;
    __syncthreads();
    if (threadIdx.x == 0) {
        float s = 0.f;
#pragma unroll
        for (int i = 0; i < 8; i++) s += sh[i];
        res = s;
    }
    __syncthreads();
    return res;
}
__device__ __forceinline__ float blockReduceMax(float v) {
    __shared__ float sh[8];
    __shared__ float res;
    int lane = threadIdx.x & 31, w = threadIdx.x >> 5;
#pragma unroll
    for (int o = 16; o; o >>= 1) v = fmaxf(v, __shfl_xor_sync(0xffffffffu, v, o));
    __syncthreads();
    if (lane == 0) sh[w] = v;
    __syncthreads();
    if (threadIdx.x == 0) {
        float s = sh[0];
#pragma unroll
        for (int i = 1; i < 8; i++) s = fmaxf(s, sh[i]);
        res = s;
    }
    __syncthreads();
    return res;
}

// ---------------- embed --------------------------------------------------------
__global__ void __launch_bounds__(256) embed_kernel(
    const int* __restrict__ ids, const float* __restrict__ emb,
    const float* __restrict__ pe, float* __restrict__ x)
{
    int row = blockIdx.x;
    int col = threadIdx.x * 4;
    int id  = ids[row];
    int s   = row & (SS - 1);
    float4 e = *(const float4*)&emb[(size_t)id * DD + col];
    float4 p = *(const float4*)&pe [(size_t)s  * DD + col];
    float4 o;
    o.x = e.x * 32.0f + p.x;
    o.y = e.y * 32.0f + p.y;
    o.z = e.z * 32.0f + p.z;
    o.w = e.w * 32.0f + p.w;
    *(float4*)&x[(size_t)row * DD + col] = o;
}

// ---------------- LayerNorm ----------------------------------------------------
__global__ void __launch_bounds__(256) ln_kernel(
    const float* __restrict__ x, const float* __restrict__ g,
    const float* __restrict__ b, float* __restrict__ out)
{
    int row = blockIdx.x;
    int col = threadIdx.x * 4;
    float4 v = *(const float4*)&x[(size_t)row * DD + col];
    float mean = blockReduceSum(v.x + v.y + v.z + v.w) * (1.0f / DD);
    float dx = v.x - mean, dy = v.y - mean, dz = v.z - mean, dw = v.w - mean;
    float var = blockReduceSum(dx*dx + dy*dy + dz*dz + dw*dw) * (1.0f / DD);
    float rstd = rsqrtf(var + 1e-6f);
    float4 gg = *(const float4*)&g[col];
    float4 bb = *(const float4*)&b[col];
    float4 o;
    o.x = dx * rstd * gg.x + bb.x;
    o.y = dy * rstd * gg.y + bb.y;
    o.z = dz * rstd * gg.z + bb.z;
    o.w = dw * rstd * gg.w + bb.w;
    *(float4*)&out[(size_t)row * DD + col] = o;
}

// ---------------- masked softmax ------------------------------------------------
__global__ void __launch_bounds__(256) softmax_kernel(
    float* __restrict__ sc, const float* __restrict__ am)
{
    size_t row = blockIdx.x;
    int b = blockIdx.x / (HH * SS);
    float* p = sc + row * SS;
    int col = threadIdx.x * 4;
    float4 v = *(float4*)&p[col];
    float4 m = *(const float4*)&am[(size_t)b * SS + col];
    v.x = (m.x == 0.f) ? -1e9f : v.x;
    v.y = (m.y == 0.f) ? -1e9f : v.y;
    v.z = (m.z == 0.f) ? -1e9f : v.z;
    v.w = (m.w == 0.f) ? -1e9f : v.w;
    float mx = blockReduceMax(fmaxf(fmaxf(v.x, v.y), fmaxf(v.z, v.w)));
    v.x = expf(v.x - mx);
    v.y = expf(v.y - mx);
    v.z = expf(v.z - mx);
    v.w = expf(v.w - mx);
    float s = blockReduceSum(v.x + v.y + v.z + v.w);
    float inv = 1.0f / s;
    v.x *= inv; v.y *= inv; v.z *= inv; v.w *= inv;
    *(float4*)&p[col] = v;
}

// ---------------- scores = Q @ K^T / 8 ------------------------------------------
__global__ void __launch_bounds__(256) scores_kernel(
    const float* __restrict__ q, const float* __restrict__ kp,
    float* __restrict__ sc)
{
    int z = blockIdx.z;
    size_t off = (size_t)(z / HH) * SS * DD + (size_t)(z % HH) * DKK;
    const float* Q  = q  + off;
    const float* Kt = kp + off;
    float* Sc = sc + (size_t)z * SS * SS;
    int bi = blockIdx.y * 64, bj = blockIdx.x * 64;
    __shared__ float Qs[16][64];
    __shared__ float Ks[16][64];
    int tid = threadIdx.x, tx = tid & 15, ty = tid >> 4;
    int lr = tid >> 2, lk = (tid & 3) * 4;
    float acc[4][4] = {};
#pragma unroll
    for (int k0 = 0; k0 < DKK; k0 += 16) {
        float4 rq = *(const float4*)&Q [(size_t)(bi + lr) * DD + k0 + lk];
        float4 rk = *(const float4*)&Kt[(size_t)(bj + lr) * DD + k0 + lk];
        __syncthreads();
        Qs[lk+0][lr] = rq.x; Qs[lk+1][lr] = rq.y; Qs[lk+2][lr] = rq.z; Qs[lk+3][lr] = rq.w;
        Ks[lk+0][lr] = rk.x; Ks[lk+1][lr] = rk.y; Ks[lk+2][lr] = rk.z; Ks[lk+3][lr] = rk.w;
        __syncthreads();
#pragma unroll
        for (int kk = 0; kk < 16; kk++) {
            float4 a = *(float4*)&Qs[kk][ty * 4];
            float4 b = *(float4*)&Ks[kk][tx * 4];
            acc[0][0] += a.x*b.x; acc[0][1] += a.x*b.y; acc[0][2] += a.x*b.z; acc[0][3] += a.x*b.w;
            acc[1][0] += a.y*b.x; acc[1][1] += a.y*b.y; acc[1][2] += a.y*b.z; acc[1][3] += a.y*b.w;
            acc[2][0] += a.z*b.x; acc[2][1] += a.z*b.y; acc[2][2] += a.z*b.z; acc[2][3] += a.z*b.w;
            acc[3][0] += a.w*b.x; acc[3][1] += a.w*b.y; acc[3][2] += a.w*b.z; acc[3][3] += a.w*b.w;
        }
    }
#pragma unroll
    for (int u = 0; u < 4; u++) {
        float4 o;
        o.x = acc[u][0] * 0.125f;
        o.y = acc[u][1] * 0.125f;
        o.z = acc[u][2] * 0.125f;
        o.w = acc[u][3] * 0.125f;
        *(float4*)&Sc[(size_t)(bi + ty*4 + u) * SS + bj + tx*4] = o;
    }
}

// ---------------- fp32 SGEMM for P@V (attention-batched) ------------------------
template<int EP, bool ATTN>
__global__ void __launch_bounds__(256) sgemm(
    const float* __restrict__ A, const float* __restrict__ Bm,
    const float* __restrict__ bias, const float* __restrict__ Rs,
    float* __restrict__ C,
    int M, int N, int K, int lda, int ldb, int ldc)
{
    if (ATTN) {
        int z = blockIdx.z;
        A += (size_t)z * (size_t)SS * SS;
        size_t off = (size_t)(z / HH) * SS * DD + (size_t)(z % HH) * DKK;
        Bm += off; C += off;
    }
    __shared__ float As[8][128];
    __shared__ float Bs[8][128];
    int tid = threadIdx.x;
    int tx = tid & 15, ty = tid >> 4;
    int bm = blockIdx.y * 128, bn = blockIdx.x * 128;
    int arow = tid >> 1,  ak   = (tid & 1) * 4;
    int brow = tid >> 5,  bcol = (tid & 31) * 4;
    const float* Aptr = A  + (size_t)(bm + arow) * lda + ak;
    const float* Bptr = Bm + (size_t)brow * ldb + bn + bcol;
    bool bok = (bn + bcol) < N;

    float acc[8][8] = {};
    int kt = K >> 3;

    float4 ra = *(const float4*)Aptr;
    float4 rb = bok ? *(const float4*)Bptr : make_float4(0.f, 0.f, 0.f, 0.f);
    As[ak+0][arow] = ra.x; As[ak+1][arow] = ra.y; As[ak+2][arow] = ra.z; As[ak+3][arow] = ra.w;
    *(float4*)&Bs[brow][bcol] = rb;
    __syncthreads();

    for (int t = 0; t < kt; t++) {
        float4 na, nb;
        if (t + 1 < kt) {
            na = *(const float4*)(Aptr + (t + 1) * 8);
            nb = bok ? *(const float4*)(Bptr + (size_t)(t + 1) * 8 * ldb)
                     : make_float4(0.f, 0.f, 0.f, 0.f);
        }
#pragma unroll
        for (int kk = 0; kk < 8; kk++) {
            float4 a0 = *(float4*)&As[kk][ty * 4];
            float4 a1 = *(float4*)&As[kk][ty * 4 + 64];
            float4 b0 = *(float4*)&Bs[kk][tx * 4];
            float4 b1 = *(float4*)&Bs[kk][tx * 4 + 64];
            float av[8] = {a0.x, a0.y, a0.z, a0.w, a1.x, a1.y, a1.z, a1.w};
            float bv[8] = {b0.x, b0.y, b0.z, b0.w, b1.x, b1.y, b1.z, b1.w};
#pragma unroll
            for (int i = 0; i < 8; i++)
#pragma unroll
                for (int j = 0; j < 8; j++)
                    acc[i][j] += av[i] * bv[j];
        }
        if (t + 1 < kt) {
            __syncthreads();
            As[ak+0][arow] = na.x; As[ak+1][arow] = na.y;
            As[ak+2][arow] = na.z; As[ak+3][arow] = na.w;
            *(float4*)&Bs[brow][bcol] = nb;
            __syncthreads();
        }
    }

#pragma unroll
    for (int ih = 0; ih < 2; ih++)
#pragma unroll
    for (int u = 0; u < 4; u++) {
        int r = bm + ih * 64 + ty * 4 + u;
#pragma unroll
        for (int jh = 0; jh < 2; jh++) {
            int c = bn + jh * 64 + tx * 4;
            if (c >= N) continue;
            float4 o;
            o.x = acc[ih*4 + u][jh*4 + 0];
            o.y = acc[ih*4 + u][jh*4 + 1];
            o.z = acc[ih*4 + u][jh*4 + 2];
            o.w = acc[ih*4 + u][jh*4 + 3];
            *(float4*)&C[(size_t)r * ldc + c] = o;
        }
    }
}

// ---------------- split fp32 -> bf16 hi/lo (activations) ------------------------
__global__ void __launch_bounds__(256) split_act(
    const float4* __restrict__ src, uint2* __restrict__ hi, uint2* __restrict__ lo)
{
    int i = blockIdx.x * 256 + threadIdx.x;
    float4 a = src[i];
    __nv_bfloat16 h0 = __float2bfloat16_rn(a.x);
    __nv_bfloat16 h1 = __float2bfloat16_rn(a.y);
    __nv_bfloat16 h2 = __float2bfloat16_rn(a.z);
    __nv_bfloat16 h3 = __float2bfloat16_rn(a.w);
    __nv_bfloat16 l0 = __float2bfloat16_rn(a.x - __bfloat162float(h0));
    __nv_bfloat16 l1 = __float2bfloat16_rn(a.y - __bfloat162float(h1));
    __nv_bfloat16 l2 = __float2bfloat16_rn(a.z - __bfloat162float(h2));
    __nv_bfloat16 l3 = __float2bfloat16_rn(a.w - __bfloat162float(h3));
    uint2 H, L;
    H.x = (uint32_t)__bfloat16_as_ushort(h0) | ((uint32_t)__bfloat16_as_ushort(h1) << 16);
    H.y = (uint32_t)__bfloat16_as_ushort(h2) | ((uint32_t)__bfloat16_as_ushort(h3) << 16);
    L.x = (uint32_t)__bfloat16_as_ushort(l0) | ((uint32_t)__bfloat16_as_ushort(l1) << 16);
    L.y = (uint32_t)__bfloat16_as_ushort(l2) | ((uint32_t)__bfloat16_as_ushort(l3) << 16);
    hi[i] = H; lo[i] = L;
}

// ---------------- split + transpose fp32 W[K,N] -> bf16 hi/lo [N,K] --------------
__global__ void __launch_bounds__(256) split_transpose(
    const float* __restrict__ src, __nv_bfloat16* __restrict__ dh,
    __nv_bfloat16* __restrict__ dl, int K, int N)
{
    __shared__ float tile[32][33];
    int k0 = blockIdx.y * 32, n0 = blockIdx.x * 32;
    int tx = threadIdx.x, ty = threadIdx.y;   // (32, 8)
#pragma unroll
    for (int i = ty; i < 32; i += 8)
        tile[i][tx] = src[(size_t)(k0 + i) * N + n0 + tx];
    __syncthreads();
#pragma unroll
    for (int i = ty; i < 32; i += 8) {
        float a = tile[tx][i];                 // src[k0+tx][n0+i]
        __nv_bfloat16 h = __float2bfloat16_rn(a);
        __nv_bfloat16 l = __float2bfloat16_rn(a - __bfloat162float(h));
        size_t di = (size_t)(n0 + i) * K + k0 + tx;
        dh[di] = h; dl[di] = l;
    }
}

// ================================================================================
// mma.sync split-bf16 GEMM: C[M,N] = A[M,K] @ Bt[N,K]^T  (+ 3-term hi/lo)
// 128x128x32 CTA tile, 8 warps (4x2), warp tile 32x64.
// smem rows padded to 80B -> conflict-free ldmatrix (5*r mod 8 is a permutation).
// EP: 0=none  2=relu(+bias)  3=+bias+residual
// blockIdx.z picks one of three {B, C} pairs (fused QKV).
// ================================================================================
struct BPtr { const __nv_bfloat16* h; const __nv_bfloat16* l; float* c; };

#define STAGE_BYTES 40960
#define MM_SMEM (2 * STAGE_BYTES)

template<int EP>
__global__ void __launch_bounds__(256, 1) mmagemm(
    const __nv_bfloat16* __restrict__ Ah, const __nv_bfloat16* __restrict__ Al,
    BPtr p0, BPtr p1, BPtr p2,
    const float* __restrict__ bias, const float* __restrict__ Rs,
    int M, int N, int K)
{
    extern __shared__ char smem[];
    uint32_t sb = smem_u32(smem);
    int z = blockIdx.z;
    BPtr P = (z == 0) ? p0 : (z == 1 ? p1 : p2);
    const __nv_bfloat16* Bh = P.h;
    const __nv_bfloat16* Bl = P.l;
    float* C = P.c;

    int tid = threadIdx.x;
    int bm = blockIdx.y * 128, bn = blockIdx.x * 128;

    const __nv_bfloat16* Abh = Ah + (size_t)bm * K;
    const __nv_bfloat16* Abl = Al + (size_t)bm * K;
    const __nv_bfloat16* Bbh = Bh + (size_t)bn * K;
    const __nv_bfloat16* Bbl = Bl + (size_t)bn * K;

    // loader: 512 16B-chunks per 128x32 tile; 4 tiles (Ah,Al,Bh,Bl)
    auto load_stage = [&](int s, int k0) {
        uint32_t st = sb + s * STAGE_BYTES;
#pragma unroll
        for (int i = 0; i < 2; i++) {
            int id = i * 256 + tid;
            int r = id >> 2, c = id & 3;
            uint32_t so = (uint32_t)(r * 80 + c * 16);
            size_t go = (size_t)r * K + k0 + c * 8;
            CP16(st +         so, (const char*)(Abh + go));
            CP16(st + 10240 + so, (const char*)(Abl + go));
            CP16(st + 20480 + so, (const char*)(Bbh + go));
            CP16(st + 30720 + so, (const char*)(Bbl + go));
        }
    };

    int wid = tid >> 5, lane = tid & 31;
    int wm = (wid & 3) * 32;          // warp M offset within tile
    int wn = (wid >> 2) * 64;         // warp N offset within tile
    int lrow  = lane & 15;
    int lcol8 = (lane >> 4) * 8;

    float acc[2][8][4];
#pragma unroll
    for (int a = 0; a < 2; a++)
#pragma unroll
        for (int b = 0; b < 8; b++)
#pragma unroll
            for (int cth = 0; cth < 4; cth++) acc[a][b][cth] = 0.f;

    load_stage(0, 0);
    CP_COMMIT();

    int NT = K >> 5;
    for (int t = 0; t < NT; t++) {
        if (t + 1 < NT) {
            load_stage((t + 1) & 1, (t + 1) * 32);
            CP_COMMIT();
            asm volatile("cp.async.wait_group 1;" ::: "memory");
        } else {
            asm volatile("cp.async.wait_group 0;" ::: "memory");
        }
        __syncthreads();

        uint32_t sA = sb + (t & 1) * STAGE_BYTES;
        uint32_t sB = sA + 20480;
#pragma unroll
        for (int ks = 0; ks < 2; ks++) {
            int k0 = ks * 16;
            uint32_t ah[2][4], al[2][4];
#pragma unroll
            for (int mf = 0; mf < 2; mf++) {
                uint32_t ad = sA + (uint32_t)((wm + mf * 16 + lrow) * 80 + (k0 + lcol8) * 2);
                LDSM4(ah[mf], ad);
                LDSM4(al[mf], ad + 10240);
            }
            uint32_t bh[8][2], bl[8][2];
#pragma unroll
            for (int nf2 = 0; nf2 < 4; nf2++) {
                uint32_t ad = sB + (uint32_t)((wn + nf2 * 16 + lrow) * 80 + (k0 + lcol8) * 2);
                uint32_t tmp[4];
                LDSM4(tmp, ad);
                bh[nf2*2][0] = tmp[0]; bh[nf2*2][1] = tmp[2];
                bh[nf2*2+1][0] = tmp[1]; bh[nf2*2+1][1] = tmp[3];
                LDSM4(tmp, ad + 10240);
                bl[nf2*2][0] = tmp[0]; bl[nf2*2][1] = tmp[2];
                bl[nf2*2+1][0] = tmp[1]; bl[nf2*2+1][1] = tmp[3];
            }
#pragma unroll
            for (int mf = 0; mf < 2; mf++)
#pragma unroll
                for (int nf = 0; nf < 8; nf++) {
                    MMA16816(acc[mf][nf], ah[mf], bh[nf]);
                    MMA16816(acc[mf][nf], ah[mf], bl[nf]);
                    MMA16816(acc[mf][nf], al[mf], bh[nf]);
                }
        }
        __syncthreads();
    }

    // epilogue
#pragma unroll
    for (int mf = 0; mf < 2; mf++) {
        int r0 = bm + wm + mf * 16 + (lane >> 2);
#pragma unroll
        for (int nf = 0; nf < 8; nf++) {
            int col = bn + wn + nf * 8 + (lane & 3) * 2;
            float2 v0 = make_float2(acc[mf][nf][0], acc[mf][nf][1]);
            float2 v1 = make_float2(acc[mf][nf][2], acc[mf][nf][3]);
            if (EP >= 1) {
                float2 bi = *(const float2*)&bias[col];
                v0.x += bi.x; v0.y += bi.y; v1.x += bi.x; v1.y += bi.y;
            }
            if (EP == 2) {
                v0.x = fmaxf(v0.x, 0.f); v0.y = fmaxf(v0.y, 0.f);
                v1.x = fmaxf(v1.x, 0.f); v1.y = fmaxf(v1.y, 0.f);
            }
            if (EP == 3) {
                float2 r0v = *(const float2*)&Rs[(size_t)r0 * N + col];
                float2 r1v = *(const float2*)&Rs[(size_t)(r0 + 8) * N + col];
                v0.x += r0v.x; v0.y += r0v.y; v1.x += r1v.x; v1.y += r1v.y;
            }
            *(float2*)&C[(size_t)r0 * N + col] = v0;
            *(float2*)&C[(size_t)(r0 + 8) * N + col] = v1;
        }
    }
}

// ---------------- host orchestration ---------------------------------------------
extern "C" void kernel_launch(void* const* d_in, const int* in_sizes, int n_in,
                              void* d_out, int out_size)
{
    const int*   ids  = (const int*)  d_in[0];
    const float* am   = (const float*)d_in[1];
    const float* emb  = (const float*)d_in[2];
    const float* pe   = (const float*)d_in[3];
    const float* wq   = (const float*)d_in[4];
    const float* wk   = (const float*)d_in[5];
    const float* wv   = (const float*)d_in[6];
    const float* wo   = (const float*)d_in[7];
    const float* bo   = (const float*)d_in[8];
    const float* w1   = (const float*)d_in[9];
    const float* b1   = (const float*)d_in[10];
    const float* w2   = (const float*)d_in[11];
    const float* b2   = (const float*)d_in[12];
    const float* ln1s = (const float*)d_in[13];
    const float* ln1b = (const float*)d_in[14];
    const float* ln2s = (const float*)d_in[15];
    const float* ln2b = (const float*)d_in[16];
    const float* lnfs = (const float*)d_in[17];
    const float* lnfb = (const float*)d_in[18];
    float* out = (float*)d_out;

    float *x, *h, *q, *k, *v, *ao, *ff, *sc;
    __nv_bfloat16 *wh, *wl, *ah, *al;
    cudaGetSymbolAddress((void**)&x,  g_x);
    cudaGetSymbolAddress((void**)&h,  g_h);
    cudaGetSymbolAddress((void**)&q,  g_q);
    cudaGetSymbolAddress((void**)&k,  g_k);
    cudaGetSymbolAddress((void**)&v,  g_v);
    cudaGetSymbolAddress((void**)&ao, g_ao);
    cudaGetSymbolAddress((void**)&ff, g_ff);
    cudaGetSymbolAddress((void**)&sc, g_sc);
    cudaGetSymbolAddress((void**)&wh, g_wh);
    cudaGetSymbolAddress((void**)&wl, g_wl);
    cudaGetSymbolAddress((void**)&ah, g_ah);
    cudaGetSymbolAddress((void**)&al, g_al);

    cudaFuncSetAttribute(mmagemm<0>, cudaFuncAttributeMaxDynamicSharedMemorySize, MM_SMEM);
    cudaFuncSetAttribute(mmagemm<2>, cudaFuncAttributeMaxDynamicSharedMemorySize, MM_SMEM);
    cudaFuncSetAttribute(mmagemm<3>, cudaFuncAttributeMaxDynamicSharedMemorySize, MM_SMEM);

    const int M = BB * SS;   // 2048

    // convert + transpose all weights to split bf16 [N,K]
    dim3 tb(32, 8);
    for (int l = 0; l < LL; l++) {
        size_t lb = (size_t)l * WL_CHUNK;
        split_transpose<<<dim3(DD/32, DD/32), tb>>>(wq + (size_t)l*DD*DD, wh + lb + OFF_Q, wl + lb + OFF_Q, DD, DD);
        split_transpose<<<dim3(DD/32, DD/32), tb>>>(wk + (size_t)l*DD*DD, wh + lb + OFF_K, wl + lb + OFF_K, DD, DD);
        split_transpose<<<dim3(DD/32, DD/32), tb>>>(wv + (size_t)l*DD*DD, wh + lb + OFF_V, wl + lb + OFF_V, DD, DD);
        split_transpose<<<dim3(DD/32, DD/32), tb>>>(wo + (size_t)l*DD*DD, wh + lb + OFF_O, wl + lb + OFF_O, DD, DD);
        split_transpose<<<dim3(FF_/32, DD/32), tb>>>(w1 + (size_t)l*DD*FF_, wh + lb + OFF_1, wl + lb + OFF_1, DD, FF_);
        split_transpose<<<dim3(DD/32, FF_/32), tb>>>(w2 + (size_t)l*FF_*DD, wh + lb + OFF_2, wl + lb + OFF_2, FF_, DD);
    }

    embed_kernel<<<M, 256>>>(ids, emb, pe, x);

    for (int l = 0; l < LL; l++) {
        size_t lb = (size_t)l * WL_CHUNK;

        // LN1 -> h, split
        ln_kernel<<<M, 256>>>(x, ln1s + l*DD, ln1b + l*DD, h);
        split_act<<<M*DD/1024, 256>>>((const float4*)h, (uint2*)ah, (uint2*)al);

        // fused Q,K,V projections (blockIdx.z selects weight/output)
        BPtr pq = { wh + lb + OFF_Q, wl + lb + OFF_Q, q };
        BPtr pk = { wh + lb + OFF_K, wl + lb + OFF_K, k };
        BPtr pv = { wh + lb + OFF_V, wl + lb + OFF_V, v };
        mmagemm<0><<<dim3(DD/128, M/128, 3), 256, MM_SMEM>>>(ah, al, pq, pk, pv,
                                                             nullptr, nullptr, M, DD, DD);

        // attention (fp32 path)
        scores_kernel<<<dim3(SS/64, SS/64, BB*HH), 256>>>(q, k, sc);
        softmax_kernel<<<BB*HH*SS, 256>>>(sc, am);
        sgemm<0, true><<<dim3(1, SS/128, BB*HH), 256>>>(sc, v, nullptr, nullptr, ao,
                                                        SS, DKK, SS, SS, DD, DD);

        // x = x + ao @ Wo + bo
        split_act<<<M*DD/1024, 256>>>((const float4*)ao, (uint2*)ah, (uint2*)al);
        BPtr po = { wh + lb + OFF_O, wl + lb + OFF_O, x };
        mmagemm<3><<<dim3(DD/128, M/128, 1), 256, MM_SMEM>>>(ah, al, po, po, po,
                                                             bo + l*DD, x, M, DD, DD);

        // LN2 -> h, split; ff = relu(h @ W1 + b1)
        ln_kernel<<<M, 256>>>(x, ln2s + l*DD, ln2b + l*DD, h);
        split_act<<<M*DD/1024, 256>>>((const float4*)h, (uint2*)ah, (uint2*)al);
        BPtr p1 = { wh + lb + OFF_1, wl + lb + OFF_1, ff };
        mmagemm<2><<<dim3(FF_/128, M/128, 1), 256, MM_SMEM>>>(ah, al, p1, p1, p1,
                                                              b1 + l*FF_, nullptr, M, FF_, DD);

        // x = x + ff @ W2 + b2
        split_act<<<M*FF_/1024, 256>>>((const float4*)ff, (uint2*)ah, (uint2*)al);
        BPtr p2 = { wh + lb + OFF_2, wl + lb + OFF_2, x };
        mmagemm<3><<<dim3(DD/128, M/128, 1), 256, MM_SMEM>>>(ah, al, p2, p2, p2,
                                                             b2 + l*DD, x, M, DD, FF_);
    }

    ln_kernel<<<M, 256>>>(x, lnfs, lnfb, out);
}

// round 5
// speedup vs baseline: 2.8173x; 1.4163x over previous
#include <cuda_runtime.h>
#include <cuda_bf16.h>
#include <cstdint>

#define BB 2
#define SS 1024
#define DD 1024
#define HH 16
#define DKK 64
#define FF_ 4096
#define LL 6

// ---------------- scratch (__device__ globals: allocation-free) --------------
__device__ float g_x [BB*SS*DD];

// weights: per layer [Wq Wk Wv Wo W1 W2], each stored TRANSPOSED [N,K], split hi/lo
#define WL_CHUNK (4*DD*DD + DD*FF_ + FF_*DD)
#define W_TOTAL  (LL * WL_CHUNK)
#define OFF_Q 0
#define OFF_K (DD*DD)
#define OFF_V (2*DD*DD)
#define OFF_O (3*DD*DD)
#define OFF_1 (4*DD*DD)
#define OFF_2 (4*DD*DD + DD*FF_)
__device__ __nv_bfloat16 g_wh[W_TOTAL];
__device__ __nv_bfloat16 g_wl[W_TOTAL];

// split activations
__device__ __nv_bfloat16 g_ah[BB*SS*DD];
__device__ __nv_bfloat16 g_al[BB*SS*DD];
__device__ __nv_bfloat16 g_fh[BB*SS*FF_];
__device__ __nv_bfloat16 g_fl[BB*SS*FF_];
__device__ __nv_bfloat16 g_qh[BB*SS*DD];
__device__ __nv_bfloat16 g_ql[BB*SS*DD];
__device__ __nv_bfloat16 g_kh[BB*SS*DD];
__device__ __nv_bfloat16 g_kl[BB*SS*DD];
__device__ __nv_bfloat16 g_vh[BB*SS*DD];
__device__ __nv_bfloat16 g_vl[BB*SS*DD];

// ---------------- PTX helpers -------------------------------------------------
__device__ __forceinline__ uint32_t smem_u32(const void* p) {
    uint32_t a;
    asm("{ .reg .u64 t; cvta.to.shared.u64 t, %1; cvt.u32.u64 %0, t; }" : "=r"(a) : "l"(p));
    return a;
}
#define CP16(d, s) asm volatile("cp.async.cg.shared.global [%0], [%1], 16;" :: "r"(d), "l"(s))
#define CP_COMMIT() asm volatile("cp.async.commit_group;" ::: "memory")

#define LDSM4(r, addr) \
    asm volatile("ldmatrix.sync.aligned.m8n8.x4.shared.b16 {%0,%1,%2,%3}, [%4];" \
        : "=r"((r)[0]), "=r"((r)[1]), "=r"((r)[2]), "=r"((r)[3]) : "r"(addr))
#define LDSM4T(r, addr) \
    asm volatile("ldmatrix.sync.aligned.m8n8.x4.trans.shared.b16 {%0,%1,%2,%3}, [%4];" \
        : "=r"((r)[0]), "=r"((r)[1]), "=r"((r)[2]), "=r"((r)[3]) : "r"(addr))

#define MMA16816(d, a, b) \
    asm volatile("mma.sync.aligned.m16n8k16.row.col.f32.bf16.bf16.f32 " \
        "{%0,%1,%2,%3}, {%4,%5,%6,%7}, {%8,%9}, {%0,%1,%2,%3};" \
        : "+f"((d)[0]), "+f"((d)[1]), "+f"((d)[2]), "+f"((d)[3]) \
        : "r"((a)[0]), "r"((a)[1]), "r"((a)[2]), "r"((a)[3]), "r"((b)[0]), "r"((b)[1]))

__device__ __forceinline__ uint32_t bf2_hi(float a, float b) {
    __nv_bfloat16 ha = __float2bfloat16_rn(a), hb = __float2bfloat16_rn(b);
    return (uint32_t)__bfloat16_as_ushort(ha) | ((uint32_t)__bfloat16_as_ushort(hb) << 16);
}
__device__ __forceinline__ uint32_t bf2_lo(float a, float b) {
    __nv_bfloat16 ha = __float2bfloat16_rn(a), hb = __float2bfloat16_rn(b);
    __nv_bfloat16 la = __float2bfloat16_rn(a - __bfloat162float(ha));
    __nv_bfloat16 lb = __float2bfloat16_rn(b - __bfloat162float(hb));
    return (uint32_t)__bfloat16_as_ushort(la) | ((uint32_t)__bfloat16_as_ushort(lb) << 16);
}

// ---------------- block reductions --------------------------------------------
__device__ __forceinline__ float blockReduceSum(float v) {
    __shared__ float sh[8];
    __shared__ float res;
    int lane = threadIdx.x & 31, w = threadIdx.x >> 5;
#pragma unroll
    for (int o = 16; o; o >>= 1) v += __shfl_xor_sync(0xffffffffu, v, o);
    __syncthreads();
    if (lane == 0) sh[w] = v;
    __syncthreads();
    if (threadIdx.x == 0) {
        float s = 0.f;
#pragma unroll
        for (int i = 0; i < 8; i++) s += sh[i];
        res = s;
    }
    __syncthreads();
    return res;
}

// ---------------- embed --------------------------------------------------------
__global__ void __launch_bounds__(256) embed_kernel(
    const int* __restrict__ ids, const float* __restrict__ emb,
    const float* __restrict__ pe, float* __restrict__ x)
{
    int row = blockIdx.x;
    int col = threadIdx.x * 4;
    int id  = ids[row];
    int s   = row & (SS - 1);
    float4 e = *(const float4*)&emb[(size_t)id * DD + col];
    float4 p = *(const float4*)&pe [(size_t)s  * DD + col];
    float4 o;
    o.x = e.x * 32.0f + p.x;
    o.y = e.y * 32.0f + p.y;
    o.z = e.z * 32.0f + p.z;
    o.w = e.w * 32.0f + p.w;
    *(float4*)&x[(size_t)row * DD + col] = o;
}

// ---------------- LayerNorm: fp32 out (final) -----------------------------------
__global__ void __launch_bounds__(256) ln_kernel(
    const float* __restrict__ x, const float* __restrict__ g,
    const float* __restrict__ b, float* __restrict__ out)
{
    int row = blockIdx.x;
    int col = threadIdx.x * 4;
    float4 v = *(const float4*)&x[(size_t)row * DD + col];
    float mean = blockReduceSum(v.x + v.y + v.z + v.w) * (1.0f / DD);
    float dx = v.x - mean, dy = v.y - mean, dz = v.z - mean, dw = v.w - mean;
    float var = blockReduceSum(dx*dx + dy*dy + dz*dz + dw*dw) * (1.0f / DD);
    float rstd = rsqrtf(var + 1e-6f);
    float4 gg = *(const float4*)&g[col];
    float4 bb = *(const float4*)&b[col];
    float4 o;
    o.x = dx * rstd * gg.x + bb.x;
    o.y = dy * rstd * gg.y + bb.y;
    o.z = dz * rstd * gg.z + bb.z;
    o.w = dw * rstd * gg.w + bb.w;
    *(float4*)&out[(size_t)row * DD + col] = o;
}

// ---------------- LayerNorm: split bf16 hi/lo out --------------------------------
__global__ void __launch_bounds__(256) ln_split_kernel(
    const float* __restrict__ x, const float* __restrict__ g,
    const float* __restrict__ b, __nv_bfloat16* __restrict__ oh,
    __nv_bfloat16* __restrict__ ol)
{
    int row = blockIdx.x;
    int col = threadIdx.x * 4;
    float4 v = *(const float4*)&x[(size_t)row * DD + col];
    float mean = blockReduceSum(v.x + v.y + v.z + v.w) * (1.0f / DD);
    float dx = v.x - mean, dy = v.y - mean, dz = v.z - mean, dw = v.w - mean;
    float var = blockReduceSum(dx*dx + dy*dy + dz*dz + dw*dw) * (1.0f / DD);
    float rstd = rsqrtf(var + 1e-6f);
    float4 gg = *(const float4*)&g[col];
    float4 bb = *(const float4*)&b[col];
    float ox = dx * rstd * gg.x + bb.x;
    float oy = dy * rstd * gg.y + bb.y;
    float oz = dz * rstd * gg.z + bb.z;
    float ow = dw * rstd * gg.w + bb.w;
    size_t idx = ((size_t)row * DD + col) >> 2;
    uint2 H = make_uint2(bf2_hi(ox, oy), bf2_hi(oz, ow));
    uint2 L = make_uint2(bf2_lo(ox, oy), bf2_lo(oz, ow));
    ((uint2*)oh)[idx] = H;
    ((uint2*)ol)[idx] = L;
}

// ---------------- split + transpose fp32 W[K,N] -> bf16 hi/lo [N,K] --------------
__global__ void __launch_bounds__(256) split_transpose(
    const float* __restrict__ src, __nv_bfloat16* __restrict__ dh,
    __nv_bfloat16* __restrict__ dl, int K, int N)
{
    __shared__ float tile[32][33];
    int k0 = blockIdx.y * 32, n0 = blockIdx.x * 32;
    int tx = threadIdx.x, ty = threadIdx.y;   // (32, 8)
#pragma unroll
    for (int i = ty; i < 32; i += 8)
        tile[i][tx] = src[(size_t)(k0 + i) * N + n0 + tx];
    __syncthreads();
#pragma unroll
    for (int i = ty; i < 32; i += 8) {
        float a = tile[tx][i];
        __nv_bfloat16 h = __float2bfloat16_rn(a);
        __nv_bfloat16 l = __float2bfloat16_rn(a - __bfloat162float(h));
        size_t di = (size_t)(n0 + i) * K + k0 + tx;
        dh[di] = h; dl[di] = l;
    }
}

// ================================================================================
// mma.sync split-bf16 GEMM: C[M,N] = A[M,K] @ Bt[N,K]^T  (3-term hi/lo)
// EP: 3 = +bias+residual -> fp32 C      (Wo, FF2)
//     4 = split bf16 hi/lo out, no bias (QKV)
//     5 = relu(+bias), split bf16 out   (FF1)
// ================================================================================
struct BPtr {
    const __nv_bfloat16* h; const __nv_bfloat16* l;
    float* c; __nv_bfloat16* ch; __nv_bfloat16* cl;
};

#define STAGE_BYTES 40960
#define MM_SMEM (2 * STAGE_BYTES)

template<int EP>
__global__ void __launch_bounds__(256, 1) mmagemm(
    const __nv_bfloat16* __restrict__ Ah, const __nv_bfloat16* __restrict__ Al,
    BPtr p0, BPtr p1, BPtr p2,
    const float* __restrict__ bias, const float* __restrict__ Rs,
    int M, int N, int K)
{
    extern __shared__ char smem[];
    uint32_t sb = smem_u32(smem);
    int z = blockIdx.z;
    BPtr P = (z == 0) ? p0 : (z == 1 ? p1 : p2);
    const __nv_bfloat16* Bh = P.h;
    const __nv_bfloat16* Bl = P.l;

    int tid = threadIdx.x;
    int bm = blockIdx.y * 128, bn = blockIdx.x * 128;

    const __nv_bfloat16* Abh = Ah + (size_t)bm * K;
    const __nv_bfloat16* Abl = Al + (size_t)bm * K;
    const __nv_bfloat16* Bbh = Bh + (size_t)bn * K;
    const __nv_bfloat16* Bbl = Bl + (size_t)bn * K;

    auto load_stage = [&](int s, int k0) {
        uint32_t st = sb + s * STAGE_BYTES;
#pragma unroll
        for (int i = 0; i < 2; i++) {
            int id = i * 256 + tid;
            int r = id >> 2, c = id & 3;
            uint32_t so = (uint32_t)(r * 80 + c * 16);
            size_t go = (size_t)r * K + k0 + c * 8;
            CP16(st +         so, (const char*)(Abh + go));
            CP16(st + 10240 + so, (const char*)(Abl + go));
            CP16(st + 20480 + so, (const char*)(Bbh + go));
            CP16(st + 30720 + so, (const char*)(Bbl + go));
        }
    };

    int wid = tid >> 5, lane = tid & 31;
    int wm = (wid & 3) * 32;
    int wn = (wid >> 2) * 64;
    int lrow  = lane & 15;
    int lcol8 = (lane >> 4) * 8;

    float acc[2][8][4];
#pragma unroll
    for (int a = 0; a < 2; a++)
#pragma unroll
        for (int b = 0; b < 8; b++)
#pragma unroll
            for (int cth = 0; cth < 4; cth++) acc[a][b][cth] = 0.f;

    load_stage(0, 0);
    CP_COMMIT();

    int NT = K >> 5;
    for (int t = 0; t < NT; t++) {
        if (t + 1 < NT) {
            load_stage((t + 1) & 1, (t + 1) * 32);
            CP_COMMIT();
            asm volatile("cp.async.wait_group 1;" ::: "memory");
        } else {
            asm volatile("cp.async.wait_group 0;" ::: "memory");
        }
        __syncthreads();

        uint32_t sA = sb + (t & 1) * STAGE_BYTES;
        uint32_t sB = sA + 20480;
#pragma unroll
        for (int ks = 0; ks < 2; ks++) {
            int k0 = ks * 16;
            uint32_t ah[2][4], al[2][4];
#pragma unroll
            for (int mf = 0; mf < 2; mf++) {
                uint32_t ad = sA + (uint32_t)((wm + mf * 16 + lrow) * 80 + (k0 + lcol8) * 2);
                LDSM4(ah[mf], ad);
                LDSM4(al[mf], ad + 10240);
            }
            uint32_t bh[8][2], bl[8][2];
#pragma unroll
            for (int nf2 = 0; nf2 < 4; nf2++) {
                uint32_t ad = sB + (uint32_t)((wn + nf2 * 16 + lrow) * 80 + (k0 + lcol8) * 2);
                uint32_t tmp[4];
                LDSM4(tmp, ad);
                bh[nf2*2][0] = tmp[0]; bh[nf2*2][1] = tmp[2];
                bh[nf2*2+1][0] = tmp[1]; bh[nf2*2+1][1] = tmp[3];
                LDSM4(tmp, ad + 10240);
                bl[nf2*2][0] = tmp[0]; bl[nf2*2][1] = tmp[2];
                bl[nf2*2+1][0] = tmp[1]; bl[nf2*2+1][1] = tmp[3];
            }
#pragma unroll
            for (int mf = 0; mf < 2; mf++)
#pragma unroll
                for (int nf = 0; nf < 8; nf++) {
                    MMA16816(acc[mf][nf], ah[mf], bh[nf]);
                    MMA16816(acc[mf][nf], ah[mf], bl[nf]);
                    MMA16816(acc[mf][nf], al[mf], bh[nf]);
                }
        }
        __syncthreads();
    }

    // epilogue
#pragma unroll
    for (int mf = 0; mf < 2; mf++) {
        int r0 = bm + wm + mf * 16 + (lane >> 2);
#pragma unroll
        for (int nf = 0; nf < 8; nf++) {
            int col = bn + wn + nf * 8 + (lane & 3) * 2;
            float2 v0 = make_float2(acc[mf][nf][0], acc[mf][nf][1]);
            float2 v1 = make_float2(acc[mf][nf][2], acc[mf][nf][3]);
            if (EP == 3 || EP == 5) {
                float2 bi = *(const float2*)&bias[col];
                v0.x += bi.x; v0.y += bi.y; v1.x += bi.x; v1.y += bi.y;
            }
            if (EP == 5) {
                v0.x = fmaxf(v0.x, 0.f); v0.y = fmaxf(v0.y, 0.f);
                v1.x = fmaxf(v1.x, 0.f); v1.y = fmaxf(v1.y, 0.f);
            }
            if (EP == 3) {
                float2 r0v = *(const float2*)&Rs[(size_t)r0 * N + col];
                float2 r1v = *(const float2*)&Rs[(size_t)(r0 + 8) * N + col];
                v0.x += r0v.x; v0.y += r0v.y; v1.x += r1v.x; v1.y += r1v.y;
                *(float2*)&P.c[(size_t)r0 * N + col] = v0;
                *(float2*)&P.c[(size_t)(r0 + 8) * N + col] = v1;
            } else {
                *(uint32_t*)&P.ch[(size_t)r0 * N + col]       = bf2_hi(v0.x, v0.y);
                *(uint32_t*)&P.ch[(size_t)(r0 + 8) * N + col] = bf2_hi(v1.x, v1.y);
                *(uint32_t*)&P.cl[(size_t)r0 * N + col]       = bf2_lo(v0.x, v0.y);
                *(uint32_t*)&P.cl[(size_t)(r0 + 8) * N + col] = bf2_lo(v1.x, v1.y);
            }
        }
    }
}

// ================================================================================
// Flash attention: per (b,h) and 128-row Q tile. Online softmax, HMMA.
// ================================================================================
#define FA_STRIDE 144
#define FA_QH 0
#define FA_QL 18432
#define FA_KH 36864
#define FA_KL 55296
#define FA_VS 73728
#define FA_MB 92160
#define FA_SMEM 92672

__global__ void __launch_bounds__(256, 1) flash_kernel(
    const __nv_bfloat16* __restrict__ qh, const __nv_bfloat16* __restrict__ ql,
    const __nv_bfloat16* __restrict__ kh, const __nv_bfloat16* __restrict__ kl,
    const __nv_bfloat16* __restrict__ vh,
    const float* __restrict__ am,
    __nv_bfloat16* __restrict__ oh, __nv_bfloat16* __restrict__ ol)
{
    extern __shared__ char smem[];
    uint32_t sb = smem_u32(smem);
    float* maskb = (float*)(smem + FA_MB);

    int qt = blockIdx.x;              // 0..7
    int bh = blockIdx.y;              // 0..31
    int b  = bh >> 4, hd = bh & 15;
    int tid = threadIdx.x;
    int wid = tid >> 5, lane = tid & 31;
    int wm = wid * 16;
    int lrow  = lane & 15;
    int lcol8 = (lane >> 4) * 8;

    size_t qrow0 = (size_t)b * SS + qt * 128;
    size_t hoff  = (size_t)hd * DKK;

    // ---- load Q tile (hi, lo) ----
#pragma unroll
    for (int i = 0; i < 4; i++) {
        int id = i * 256 + tid;       // 0..1023
        int r = id >> 3, c = id & 7;
        uint32_t so = (uint32_t)(r * FA_STRIDE + c * 16);
        size_t go = (qrow0 + r) * DD + hoff + c * 8;
        CP16(sb + FA_QH + so, (const char*)(qh + go));
        CP16(sb + FA_QL + so, (const char*)(ql + go));
    }
    // ---- load K/V tile 0 ----
#pragma unroll
    for (int i = 0; i < 4; i++) {
        int id = i * 256 + tid;
        int r = id >> 3, c = id & 7;
        uint32_t so = (uint32_t)(r * FA_STRIDE + c * 16);
        size_t go = ((size_t)b * SS + r) * DD + hoff + c * 8;
        CP16(sb + FA_KH + so, (const char*)(kh + go));
        CP16(sb + FA_KL + so, (const char*)(kl + go));
        CP16(sb + FA_VS + so, (const char*)(vh + go));
    }
    CP_COMMIT();
    if (tid < 128) {
        float m = am[(size_t)b * SS + tid];
        maskb[tid] = (m == 0.f) ? -1e9f : 0.f;
    }

    float m0 = -1e30f, m1 = -1e30f, s0 = 0.f, s1 = 0.f;
    float oacc[8][4];
#pragma unroll
    for (int i = 0; i < 8; i++)
#pragma unroll
        for (int j = 0; j < 4; j++) oacc[i][j] = 0.f;

    for (int t = 0; t < 8; t++) {
        asm volatile("cp.async.wait_group 0;" ::: "memory");
        __syncthreads();

        // ---- scores: S[16][128] fp32 ----
        float sacc[16][4];
#pragma unroll
        for (int i = 0; i < 16; i++)
#pragma unroll
            for (int j = 0; j < 4; j++) sacc[i][j] = 0.f;

#pragma unroll
        for (int kf = 0; kf < 4; kf++) {
            uint32_t aqh[4], aql[4];
            uint32_t ad = sb + FA_QH + (uint32_t)((wm + lrow) * FA_STRIDE + (kf * 16 + lcol8) * 2);
            LDSM4(aqh, ad);
            LDSM4(aql, ad + (FA_QL - FA_QH));
#pragma unroll
            for (int nf2 = 0; nf2 < 8; nf2++) {
                uint32_t kd = sb + FA_KH + (uint32_t)((nf2 * 16 + lrow) * FA_STRIDE + (kf * 16 + lcol8) * 2);
                uint32_t tmp[4];
                uint32_t bhf[2][2], blf[2][2];
                LDSM4(tmp, kd);
                bhf[0][0] = tmp[0]; bhf[0][1] = tmp[2];
                bhf[1][0] = tmp[1]; bhf[1][1] = tmp[3];
                LDSM4(tmp, kd + (FA_KL - FA_KH));
                blf[0][0] = tmp[0]; blf[0][1] = tmp[2];
                blf[1][0] = tmp[1]; blf[1][1] = tmp[3];
#pragma unroll
                for (int u = 0; u < 2; u++) {
                    MMA16816(sacc[nf2*2+u], aqh, bhf[u]);
                    MMA16816(sacc[nf2*2+u], aqh, blf[u]);
                    MMA16816(sacc[nf2*2+u], aql, bhf[u]);
                }
            }
        }

        // ---- online softmax ----
        float mn0 = m0, mn1 = m1;
#pragma unroll
        for (int nf = 0; nf < 16; nf++) {
            int col = nf * 8 + (lane & 3) * 2;
            float b0 = maskb[col], b1 = maskb[col + 1];
            sacc[nf][0] = sacc[nf][0] * 0.125f + b0;
            sacc[nf][1] = sacc[nf][1] * 0.125f + b1;
            sacc[nf][2] = sacc[nf][2] * 0.125f + b0;
            sacc[nf][3] = sacc[nf][3] * 0.125f + b1;
            mn0 = fmaxf(mn0, fmaxf(sacc[nf][0], sacc[nf][1]));
            mn1 = fmaxf(mn1, fmaxf(sacc[nf][2], sacc[nf][3]));
        }
        mn0 = fmaxf(mn0, __shfl_xor_sync(0xffffffffu, mn0, 1));
        mn0 = fmaxf(mn0, __shfl_xor_sync(0xffffffffu, mn0, 2));
        mn1 = fmaxf(mn1, __shfl_xor_sync(0xffffffffu, mn1, 1));
        mn1 = fmaxf(mn1, __shfl_xor_sync(0xffffffffu, mn1, 2));
        float alpha0 = __expf(m0 - mn0);
        float alpha1 = __expf(m1 - mn1);
        m0 = mn0; m1 = mn1;
        float rs0 = 0.f, rs1 = 0.f;
#pragma unroll
        for (int nf = 0; nf < 16; nf++) {
            sacc[nf][0] = __expf(sacc[nf][0] - mn0);
            sacc[nf][1] = __expf(sacc[nf][1] - mn0);
            sacc[nf][2] = __expf(sacc[nf][2] - mn1);
            sacc[nf][3] = __expf(sacc[nf][3] - mn1);
            rs0 += sacc[nf][0] + sacc[nf][1];
            rs1 += sacc[nf][2] + sacc[nf][3];
        }
        rs0 += __shfl_xor_sync(0xffffffffu, rs0, 1);
        rs0 += __shfl_xor_sync(0xffffffffu, rs0, 2);
        rs1 += __shfl_xor_sync(0xffffffffu, rs1, 1);
        rs1 += __shfl_xor_sync(0xffffffffu, rs1, 2);
        s0 = s0 * alpha0 + rs0;
        s1 = s1 * alpha1 + rs1;
#pragma unroll
        for (int i = 0; i < 8; i++) {
            oacc[i][0] *= alpha0; oacc[i][1] *= alpha0;
            oacc[i][2] *= alpha1; oacc[i][3] *= alpha1;
        }

        // ---- O += P @ V ----  (dv2: 4 groups x 16 dv = all 64 dims)
#pragma unroll
        for (int kk = 0; kk < 8; kk++) {
            uint32_t ap[4];
            ap[0] = bf2_hi(sacc[2*kk][0],   sacc[2*kk][1]);
            ap[1] = bf2_hi(sacc[2*kk][2],   sacc[2*kk][3]);
            ap[2] = bf2_hi(sacc[2*kk+1][0], sacc[2*kk+1][1]);
            ap[3] = bf2_hi(sacc[2*kk+1][2], sacc[2*kk+1][3]);
#pragma unroll
            for (int dv2 = 0; dv2 < 4; dv2++) {
                uint32_t tmp[4];
                uint32_t vd = sb + FA_VS + (uint32_t)((kk * 16 + lrow) * FA_STRIDE + (dv2 * 16 + lcol8) * 2);
                LDSM4T(tmp, vd);
                uint32_t bv0[2] = { tmp[0], tmp[1] };
                uint32_t bv1[2] = { tmp[2], tmp[3] };
                MMA16816(oacc[dv2*2],   ap, bv0);
                MMA16816(oacc[dv2*2+1], ap, bv1);
            }
        }

        __syncthreads();
        if (t + 1 < 8) {
#pragma unroll
            for (int i = 0; i < 4; i++) {
                int id = i * 256 + tid;
                int r = id >> 3, c = id & 7;
                uint32_t so = (uint32_t)(r * FA_STRIDE + c * 16);
                size_t go = ((size_t)b * SS + (t + 1) * 128 + r) * DD + hoff + c * 8;
                CP16(sb + FA_KH + so, (const char*)(kh + go));
                CP16(sb + FA_KL + so, (const char*)(kl + go));
                CP16(sb + FA_VS + so, (const char*)(vh + go));
            }
            CP_COMMIT();
            if (tid < 128) {
                float m = am[(size_t)b * SS + (t + 1) * 128 + tid];
                maskb[tid] = (m == 0.f) ? -1e9f : 0.f;
            }
        }
    }

    // ---- epilogue: O /= s, split store ----
    float inv0 = 1.0f / s0, inv1 = 1.0f / s1;
    int r0 = (int)qrow0 + wm + (lane >> 2);
#pragma unroll
    for (int nf = 0; nf < 8; nf++) {
        int col = (int)hoff + nf * 8 + (lane & 3) * 2;
        float a0 = oacc[nf][0] * inv0, a1 = oacc[nf][1] * inv0;
        float a2 = oacc[nf][2] * inv1, a3 = oacc[nf][3] * inv1;
        *(uint32_t*)&oh[(size_t)r0 * DD + col]       = bf2_hi(a0, a1);
        *(uint32_t*)&ol[(size_t)r0 * DD + col]       = bf2_lo(a0, a1);
        *(uint32_t*)&oh[(size_t)(r0 + 8) * DD + col] = bf2_hi(a2, a3);
        *(uint32_t*)&ol[(size_t)(r0 + 8) * DD + col] = bf2_lo(a2, a3);
    }
}

// ---------------- host orchestration ---------------------------------------------
extern "C" void kernel_launch(void* const* d_in, const int* in_sizes, int n_in,
                              void* d_out, int out_size)
{
    const int*   ids  = (const int*)  d_in[0];
    const float* am   = (const float*)d_in[1];
    const float* emb  = (const float*)d_in[2];
    const float* pe   = (const float*)d_in[3];
    const float* wq   = (const float*)d_in[4];
    const float* wk   = (const float*)d_in[5];
    const float* wv   = (const float*)d_in[6];
    const float* wo   = (const float*)d_in[7];
    const float* bo   = (const float*)d_in[8];
    const float* w1   = (const float*)d_in[9];
    const float* b1   = (const float*)d_in[10];
    const float* w2   = (const float*)d_in[11];
    const float* b2   = (const float*)d_in[12];
    const float* ln1s = (const float*)d_in[13];
    const float* ln1b = (const float*)d_in[14];
    const float* ln2s = (const float*)d_in[15];
    const float* ln2b = (const float*)d_in[16];
    const float* lnfs = (const float*)d_in[17];
    const float* lnfb = (const float*)d_in[18];
    float* out = (float*)d_out;

    float *x;
    __nv_bfloat16 *wh, *wl, *ah, *al, *fh, *fl, *qh_, *ql_, *kh_, *kl_, *vh_, *vl_;
    cudaGetSymbolAddress((void**)&x,   g_x);
    cudaGetSymbolAddress((void**)&wh,  g_wh);
    cudaGetSymbolAddress((void**)&wl,  g_wl);
    cudaGetSymbolAddress((void**)&ah,  g_ah);
    cudaGetSymbolAddress((void**)&al,  g_al);
    cudaGetSymbolAddress((void**)&fh,  g_fh);
    cudaGetSymbolAddress((void**)&fl,  g_fl);
    cudaGetSymbolAddress((void**)&qh_, g_qh);
    cudaGetSymbolAddress((void**)&ql_, g_ql);
    cudaGetSymbolAddress((void**)&kh_, g_kh);
    cudaGetSymbolAddress((void**)&kl_, g_kl);
    cudaGetSymbolAddress((void**)&vh_, g_vh);
    cudaGetSymbolAddress((void**)&vl_, g_vl);

    cudaFuncSetAttribute(mmagemm<3>, cudaFuncAttributeMaxDynamicSharedMemorySize, MM_SMEM);
    cudaFuncSetAttribute(mmagemm<4>, cudaFuncAttributeMaxDynamicSharedMemorySize, MM_SMEM);
    cudaFuncSetAttribute(mmagemm<5>, cudaFuncAttributeMaxDynamicSharedMemorySize, MM_SMEM);
    cudaFuncSetAttribute(flash_kernel, cudaFuncAttributeMaxDynamicSharedMemorySize, FA_SMEM);

    const int M = BB * SS;

    dim3 tb(32, 8);
    for (int l = 0; l < LL; l++) {
        size_t lb = (size_t)l * WL_CHUNK;
        split_transpose<<<dim3(DD/32, DD/32), tb>>>(wq + (size_t)l*DD*DD, wh + lb + OFF_Q, wl + lb + OFF_Q, DD, DD);
        split_transpose<<<dim3(DD/32, DD/32), tb>>>(wk + (size_t)l*DD*DD, wh + lb + OFF_K, wl + lb + OFF_K, DD, DD);
        split_transpose<<<dim3(DD/32, DD/32), tb>>>(wv + (size_t)l*DD*DD, wh + lb + OFF_V, wl + lb + OFF_V, DD, DD);
        split_transpose<<<dim3(DD/32, DD/32), tb>>>(wo + (size_t)l*DD*DD, wh + lb + OFF_O, wl + lb + OFF_O, DD, DD);
        split_transpose<<<dim3(FF_/32, DD/32), tb>>>(w1 + (size_t)l*DD*FF_, wh + lb + OFF_1, wl + lb + OFF_1, DD, FF_);
        split_transpose<<<dim3(DD/32, FF_/32), tb>>>(w2 + (size_t)l*FF_*DD, wh + lb + OFF_2, wl + lb + OFF_2, FF_, DD);
    }

    embed_kernel<<<M, 256>>>(ids, emb, pe, x);

    for (int l = 0; l < LL; l++) {
        size_t lb = (size_t)l * WL_CHUNK;

        // LN1 -> split
        ln_split_kernel<<<M, 256>>>(x, ln1s + l*DD, ln1b + l*DD, ah, al);

        // fused Q,K,V projections -> split bf16
        BPtr pq = { wh + lb + OFF_Q, wl + lb + OFF_Q, nullptr, qh_, ql_ };
        BPtr pk = { wh + lb + OFF_K, wl + lb + OFF_K, nullptr, kh_, kl_ };
        BPtr pv = { wh + lb + OFF_V, wl + lb + OFF_V, nullptr, vh_, vl_ };
        mmagemm<4><<<dim3(DD/128, M/128, 3), 256, MM_SMEM>>>(ah, al, pq, pk, pv,
                                                             nullptr, nullptr, M, DD, DD);

        // flash attention -> split attn out in (ah, al)
        flash_kernel<<<dim3(SS/128, BB*HH), 256, FA_SMEM>>>(qh_, ql_, kh_, kl_, vh_,
                                                            am, ah, al);

        // x = x + attn @ Wo + bo
        BPtr po = { wh + lb + OFF_O, wl + lb + OFF_O, x, nullptr, nullptr };
        mmagemm<3><<<dim3(DD/128, M/128, 1), 256, MM_SMEM>>>(ah, al, po, po, po,
                                                             bo + l*DD, x, M, DD, DD);

        // LN2 -> split; ff = relu(h @ W1 + b1) -> split
        ln_split_kernel<<<M, 256>>>(x, ln2s + l*DD, ln2b + l*DD, ah, al);
        BPtr p1 = { wh + lb + OFF_1, wl + lb + OFF_1, nullptr, fh, fl };
        mmagemm<5><<<dim3(FF_/128, M/128, 1), 256, MM_SMEM>>>(ah, al, p1, p1, p1,
                                                              b1 + l*FF_, nullptr, M, FF_, DD);

        // x = x + ff @ W2 + b2
        BPtr p2 = { wh + lb + OFF_2, wl + lb + OFF_2, x, nullptr, nullptr };
        mmagemm<3><<<dim3(DD/128, M/128, 1), 256, MM_SMEM>>>(fh, fl, p2, p2, p2,
                                                             b2 + l*DD, x, M, DD, FF_);
    }

    ln_kernel<<<M, 256>>>(x, lnfs, lnfb, out);
}

// round 6
// speedup vs baseline: 2.9490x; 1.0467x over previous
#include <cuda_runtime.h>
#include <cuda_bf16.h>
#include <cstdint>

#define BB 2
#define SS 1024
#define DD 1024
#define HH 16
#define DKK 64
#define FF_ 4096
#define LL 6

// ---------------- scratch (__device__ globals: allocation-free) --------------
__device__ float g_x [BB*SS*DD];

// weights: per layer [Wq Wk Wv Wo W1 W2], each stored TRANSPOSED [N,K], split hi/lo
#define WL_CHUNK (4*DD*DD + DD*FF_ + FF_*DD)
#define W_TOTAL  (LL * WL_CHUNK)
#define OFF_Q 0
#define OFF_K (DD*DD)
#define OFF_V (2*DD*DD)
#define OFF_O (3*DD*DD)
#define OFF_1 (4*DD*DD)
#define OFF_2 (4*DD*DD + DD*FF_)
__device__ __nv_bfloat16 g_wh[W_TOTAL];
__device__ __nv_bfloat16 g_wl[W_TOTAL];

// split activations
__device__ __nv_bfloat16 g_ah[BB*SS*DD];
__device__ __nv_bfloat16 g_al[BB*SS*DD];
__device__ __nv_bfloat16 g_fh[BB*SS*FF_];
__device__ __nv_bfloat16 g_fl[BB*SS*FF_];
__device__ __nv_bfloat16 g_qh[BB*SS*DD];
__device__ __nv_bfloat16 g_ql[BB*SS*DD];
__device__ __nv_bfloat16 g_kh[BB*SS*DD];
__device__ __nv_bfloat16 g_kl[BB*SS*DD];
__device__ __nv_bfloat16 g_vh[BB*SS*DD];
__device__ __nv_bfloat16 g_vl[BB*SS*DD];

// ---------------- PTX helpers -------------------------------------------------
__device__ __forceinline__ uint32_t smem_u32(const void* p) {
    uint32_t a;
    asm("{ .reg .u64 t; cvta.to.shared.u64 t, %1; cvt.u32.u64 %0, t; }" : "=r"(a) : "l"(p));
    return a;
}
#define CP16(d, s) asm volatile("cp.async.cg.shared.global [%0], [%1], 16;" :: "r"(d), "l"(s))
#define CP_COMMIT() asm volatile("cp.async.commit_group;" ::: "memory")

#define LDSM4(r, addr) \
    asm volatile("ldmatrix.sync.aligned.m8n8.x4.shared.b16 {%0,%1,%2,%3}, [%4];" \
        : "=r"((r)[0]), "=r"((r)[1]), "=r"((r)[2]), "=r"((r)[3]) : "r"(addr))
#define LDSM4T(r, addr) \
    asm volatile("ldmatrix.sync.aligned.m8n8.x4.trans.shared.b16 {%0,%1,%2,%3}, [%4];" \
        : "=r"((r)[0]), "=r"((r)[1]), "=r"((r)[2]), "=r"((r)[3]) : "r"(addr))

#define MMA16816(d, a, b) \
    asm volatile("mma.sync.aligned.m16n8k16.row.col.f32.bf16.bf16.f32 " \
        "{%0,%1,%2,%3}, {%4,%5,%6,%7}, {%8,%9}, {%0,%1,%2,%3};" \
        : "+f"((d)[0]), "+f"((d)[1]), "+f"((d)[2]), "+f"((d)[3]) \
        : "r"((a)[0]), "r"((a)[1]), "r"((a)[2]), "r"((a)[3]), "r"((b)[0]), "r"((b)[1]))

__device__ __forceinline__ uint32_t bf2_hi(float a, float b) {
    __nv_bfloat16 ha = __float2bfloat16_rn(a), hb = __float2bfloat16_rn(b);
    return (uint32_t)__bfloat16_as_ushort(ha) | ((uint32_t)__bfloat16_as_ushort(hb) << 16);
}
__device__ __forceinline__ uint32_t bf2_lo(float a, float b) {
    __nv_bfloat16 ha = __float2bfloat16_rn(a), hb = __float2bfloat16_rn(b);
    __nv_bfloat16 la = __float2bfloat16_rn(a - __bfloat162float(ha));
    __nv_bfloat16 lb = __float2bfloat16_rn(b - __bfloat162float(hb));
    return (uint32_t)__bfloat16_as_ushort(la) | ((uint32_t)__bfloat16_as_ushort(lb) << 16);
}

// ---------------- block reductions --------------------------------------------
__device__ __forceinline__ float blockReduceSum(float v) {
    __shared__ float sh[8];
    __shared__ float res;
    int lane = threadIdx.x & 31, w = threadIdx.x >> 5;
#pragma unroll
    for (int o = 16; o; o >>= 1) v += __shfl_xor_sync(0xffffffffu, v, o);
    __syncthreads();
    if (lane == 0) sh[w] = v;
    __syncthreads();
    if (threadIdx.x == 0) {
        float s = 0.f;
#pragma unroll
        for (int i = 0; i < 8; i++) s += sh[i];
        res = s;
    }
    __syncthreads();
    return res;
}

// ---------------- embed --------------------------------------------------------
__global__ void __launch_bounds__(256) embed_kernel(
    const int* __restrict__ ids, const float* __restrict__ emb,
    const float* __restrict__ pe, float* __restrict__ x)
{
    int row = blockIdx.x;
    int col = threadIdx.x * 4;
    int id  = ids[row];
    int s   = row & (SS - 1);
    float4 e = *(const float4*)&emb[(size_t)id * DD + col];
    float4 p = *(const float4*)&pe [(size_t)s  * DD + col];
    float4 o;
    o.x = e.x * 32.0f + p.x;
    o.y = e.y * 32.0f + p.y;
    o.z = e.z * 32.0f + p.z;
    o.w = e.w * 32.0f + p.w;
    *(float4*)&x[(size_t)row * DD + col] = o;
}

// ---------------- LayerNorm: fp32 out (final) -----------------------------------
__global__ void __launch_bounds__(256) ln_kernel(
    const float* __restrict__ x, const float* __restrict__ g,
    const float* __restrict__ b, float* __restrict__ out)
{
    int row = blockIdx.x;
    int col = threadIdx.x * 4;
    float4 v = *(const float4*)&x[(size_t)row * DD + col];
    float mean = blockReduceSum(v.x + v.y + v.z + v.w) * (1.0f / DD);
    float dx = v.x - mean, dy = v.y - mean, dz = v.z - mean, dw = v.w - mean;
    float var = blockReduceSum(dx*dx + dy*dy + dz*dz + dw*dw) * (1.0f / DD);
    float rstd = rsqrtf(var + 1e-6f);
    float4 gg = *(const float4*)&g[col];
    float4 bb = *(const float4*)&b[col];
    float4 o;
    o.x = dx * rstd * gg.x + bb.x;
    o.y = dy * rstd * gg.y + bb.y;
    o.z = dz * rstd * gg.z + bb.z;
    o.w = dw * rstd * gg.w + bb.w;
    *(float4*)&out[(size_t)row * DD + col] = o;
}

// ---------------- LayerNorm: split bf16 hi/lo out --------------------------------
__global__ void __launch_bounds__(256) ln_split_kernel(
    const float* __restrict__ x, const float* __restrict__ g,
    const float* __restrict__ b, __nv_bfloat16* __restrict__ oh,
    __nv_bfloat16* __restrict__ ol)
{
    int row = blockIdx.x;
    int col = threadIdx.x * 4;
    float4 v = *(const float4*)&x[(size_t)row * DD + col];
    float mean = blockReduceSum(v.x + v.y + v.z + v.w) * (1.0f / DD);
    float dx = v.x - mean, dy = v.y - mean, dz = v.z - mean, dw = v.w - mean;
    float var = blockReduceSum(dx*dx + dy*dy + dz*dz + dw*dw) * (1.0f / DD);
    float rstd = rsqrtf(var + 1e-6f);
    float4 gg = *(const float4*)&g[col];
    float4 bb = *(const float4*)&b[col];
    float ox = dx * rstd * gg.x + bb.x;
    float oy = dy * rstd * gg.y + bb.y;
    float oz = dz * rstd * gg.z + bb.z;
    float ow = dw * rstd * gg.w + bb.w;
    size_t idx = ((size_t)row * DD + col) >> 2;
    uint2 H = make_uint2(bf2_hi(ox, oy), bf2_hi(oz, ow));
    uint2 L = make_uint2(bf2_lo(ox, oy), bf2_lo(oz, ow));
    ((uint2*)oh)[idx] = H;
    ((uint2*)ol)[idx] = L;
}

// ---------------- batched weight prep -------------------------------------------
// All 24 DxD mats (Wq,Wk,Wv,Wo x 6 layers) in one launch; z = l*4 + which.
__global__ void __launch_bounds__(256) prep_qkvo(
    const float* __restrict__ wq, const float* __restrict__ wk,
    const float* __restrict__ wv, const float* __restrict__ wo,
    __nv_bfloat16* __restrict__ dh, __nv_bfloat16* __restrict__ dl)
{
    __shared__ float tile[32][33];
    int z = blockIdx.z, l = z >> 2, ws = z & 3;
    const float* src = (ws == 0 ? wq : ws == 1 ? wk : ws == 2 ? wv : wo) + (size_t)l * DD * DD;
    size_t dbase = (size_t)l * WL_CHUNK + (size_t)ws * DD * DD;
    int k0 = blockIdx.y * 32, n0 = blockIdx.x * 32;
    int tx = threadIdx.x & 31, ty = threadIdx.x >> 5;
#pragma unroll
    for (int i = ty; i < 32; i += 8)
        tile[i][tx] = src[(size_t)(k0 + i) * DD + n0 + tx];
    __syncthreads();
#pragma unroll
    for (int i = ty; i < 32; i += 8) {
        float a = tile[tx][i];
        __nv_bfloat16 h = __float2bfloat16_rn(a);
        __nv_bfloat16 lo = __float2bfloat16_rn(a - __bfloat162float(h));
        size_t di = dbase + (size_t)(n0 + i) * DD + k0 + tx;
        dh[di] = h; dl[di] = lo;
    }
}

// W1 or W2 across all layers; z = layer. src [K,N] -> dst [N,K] at layer offset.
__global__ void __launch_bounds__(256) prep_ff(
    const float* __restrict__ src, __nv_bfloat16* __restrict__ dh,
    __nv_bfloat16* __restrict__ dl, int dstOff, int K, int N)
{
    __shared__ float tile[32][33];
    int l = blockIdx.z;
    const float* s = src + (size_t)l * K * N;
    size_t dbase = (size_t)l * WL_CHUNK + dstOff;
    int k0 = blockIdx.y * 32, n0 = blockIdx.x * 32;
    int tx = threadIdx.x & 31, ty = threadIdx.x >> 5;
#pragma unroll
    for (int i = ty; i < 32; i += 8)
        tile[i][tx] = s[(size_t)(k0 + i) * N + n0 + tx];
    __syncthreads();
#pragma unroll
    for (int i = ty; i < 32; i += 8) {
        float a = tile[tx][i];
        __nv_bfloat16 h = __float2bfloat16_rn(a);
        __nv_bfloat16 lo = __float2bfloat16_rn(a - __bfloat162float(h));
        size_t di = dbase + (size_t)(n0 + i) * K + k0 + tx;
        dh[di] = h; dl[di] = lo;
    }
}

// ================================================================================
// mma.sync split-bf16 GEMM: C[M,N] = A[M,K] @ Bt[N,K]^T  (3-term hi/lo)
// 3-stage cp.async pipeline, ONE __syncthreads per k-chunk.
// EP: 3 = +bias+residual -> fp32 C      (Wo, FF2)
//     4 = split bf16 hi/lo out, no bias (QKV)
//     5 = relu(+bias), split bf16 out   (FF1)
// ================================================================================
struct BPtr {
    const __nv_bfloat16* h; const __nv_bfloat16* l;
    float* c; __nv_bfloat16* ch; __nv_bfloat16* cl;
};

#define STAGE_BYTES 40960
#define MM_SMEM (3 * STAGE_BYTES)

template<int EP>
__global__ void __launch_bounds__(256, 1) mmagemm(
    const __nv_bfloat16* __restrict__ Ah, const __nv_bfloat16* __restrict__ Al,
    BPtr p0, BPtr p1, BPtr p2,
    const float* __restrict__ bias, const float* __restrict__ Rs,
    int M, int N, int K)
{
    extern __shared__ char smem[];
    uint32_t sb = smem_u32(smem);
    int z = blockIdx.z;
    BPtr P = (z == 0) ? p0 : (z == 1 ? p1 : p2);
    const __nv_bfloat16* Bh = P.h;
    const __nv_bfloat16* Bl = P.l;

    int tid = threadIdx.x;
    int bm = blockIdx.y * 128, bn = blockIdx.x * 128;

    const __nv_bfloat16* Abh = Ah + (size_t)bm * K;
    const __nv_bfloat16* Abl = Al + (size_t)bm * K;
    const __nv_bfloat16* Bbh = Bh + (size_t)bn * K;
    const __nv_bfloat16* Bbl = Bl + (size_t)bn * K;

    auto load_stage = [&](int s, int k0) {
        uint32_t st = sb + s * STAGE_BYTES;
#pragma unroll
        for (int i = 0; i < 2; i++) {
            int id = i * 256 + tid;
            int r = id >> 2, c = id & 3;
            uint32_t so = (uint32_t)(r * 80 + c * 16);
            size_t go = (size_t)r * K + k0 + c * 8;
            CP16(st +         so, (const char*)(Abh + go));
            CP16(st + 10240 + so, (const char*)(Abl + go));
            CP16(st + 20480 + so, (const char*)(Bbh + go));
            CP16(st + 30720 + so, (const char*)(Bbl + go));
        }
    };

    int wid = tid >> 5, lane = tid & 31;
    int wm = (wid & 3) * 32;
    int wn = (wid >> 2) * 64;
    int lrow  = lane & 15;
    int lcol8 = (lane >> 4) * 8;

    float acc[2][8][4];
#pragma unroll
    for (int a = 0; a < 2; a++)
#pragma unroll
        for (int b = 0; b < 8; b++)
#pragma unroll
            for (int cth = 0; cth < 4; cth++) acc[a][b][cth] = 0.f;

    int NT = K >> 5;
    load_stage(0, 0);
    CP_COMMIT();
    if (NT > 1) { load_stage(1, 32); CP_COMMIT(); }

    for (int t = 0; t < NT; t++) {
        if (t + 1 < NT) asm volatile("cp.async.wait_group 1;" ::: "memory");
        else            asm volatile("cp.async.wait_group 0;" ::: "memory");
        __syncthreads();
        if (t + 2 < NT) { load_stage((t + 2) % 3, (t + 2) * 32); CP_COMMIT(); }

        uint32_t sA = sb + (uint32_t)(t % 3) * STAGE_BYTES;
        uint32_t sB = sA + 20480;
#pragma unroll
        for (int ks = 0; ks < 2; ks++) {
            int k0 = ks * 16;
            uint32_t ah[2][4], al[2][4];
#pragma unroll
            for (int mf = 0; mf < 2; mf++) {
                uint32_t ad = sA + (uint32_t)((wm + mf * 16 + lrow) * 80 + (k0 + lcol8) * 2);
                LDSM4(ah[mf], ad);
                LDSM4(al[mf], ad + 10240);
            }
            uint32_t bh[8][2], bl[8][2];
#pragma unroll
            for (int nf2 = 0; nf2 < 4; nf2++) {
                uint32_t ad = sB + (uint32_t)((wn + nf2 * 16 + lrow) * 80 + (k0 + lcol8) * 2);
                uint32_t tmp[4];
                LDSM4(tmp, ad);
                bh[nf2*2][0] = tmp[0]; bh[nf2*2][1] = tmp[2];
                bh[nf2*2+1][0] = tmp[1]; bh[nf2*2+1][1] = tmp[3];
                LDSM4(tmp, ad + 10240);
                bl[nf2*2][0] = tmp[0]; bl[nf2*2][1] = tmp[2];
                bl[nf2*2+1][0] = tmp[1]; bl[nf2*2+1][1] = tmp[3];
            }
#pragma unroll
            for (int mf = 0; mf < 2; mf++)
#pragma unroll
                for (int nf = 0; nf < 8; nf++) {
                    MMA16816(acc[mf][nf], ah[mf], bh[nf]);
                    MMA16816(acc[mf][nf], ah[mf], bl[nf]);
                    MMA16816(acc[mf][nf], al[mf], bh[nf]);
                }
        }
    }

    // epilogue
#pragma unroll
    for (int mf = 0; mf < 2; mf++) {
        int r0 = bm + wm + mf * 16 + (lane >> 2);
#pragma unroll
        for (int nf = 0; nf < 8; nf++) {
            int col = bn + wn + nf * 8 + (lane & 3) * 2;
            float2 v0 = make_float2(acc[mf][nf][0], acc[mf][nf][1]);
            float2 v1 = make_float2(acc[mf][nf][2], acc[mf][nf][3]);
            if (EP == 3 || EP == 5) {
                float2 bi = *(const float2*)&bias[col];
                v0.x += bi.x; v0.y += bi.y; v1.x += bi.x; v1.y += bi.y;
            }
            if (EP == 5) {
                v0.x = fmaxf(v0.x, 0.f); v0.y = fmaxf(v0.y, 0.f);
                v1.x = fmaxf(v1.x, 0.f); v1.y = fmaxf(v1.y, 0.f);
            }
            if (EP == 3) {
                float2 r0v = *(const float2*)&Rs[(size_t)r0 * N + col];
                float2 r1v = *(const float2*)&Rs[(size_t)(r0 + 8) * N + col];
                v0.x += r0v.x; v0.y += r0v.y; v1.x += r1v.x; v1.y += r1v.y;
                *(float2*)&P.c[(size_t)r0 * N + col] = v0;
                *(float2*)&P.c[(size_t)(r0 + 8) * N + col] = v1;
            } else {
                *(uint32_t*)&P.ch[(size_t)r0 * N + col]       = bf2_hi(v0.x, v0.y);
                *(uint32_t*)&P.ch[(size_t)(r0 + 8) * N + col] = bf2_hi(v1.x, v1.y);
                *(uint32_t*)&P.cl[(size_t)r0 * N + col]       = bf2_lo(v0.x, v0.y);
                *(uint32_t*)&P.cl[(size_t)(r0 + 8) * N + col] = bf2_lo(v1.x, v1.y);
            }
        }
    }
}

// ================================================================================
// Flash attention: per (b,h) and 128-row Q tile. Online softmax, HMMA.
// Double-buffered KV tiles: load of tile t+1 overlaps compute of tile t.
// ================================================================================
#define FA_STRIDE 144
#define FA_QH 0
#define FA_QL 18432
#define FA_KV0 36864
#define FA_KVSTAGE 55296      /* KH +0, KL +18432, V +36864 */
#define FA_MB 147456          /* 2 x 128 floats */
#define FA_SMEM 148480

__global__ void __launch_bounds__(256, 1) flash_kernel(
    const __nv_bfloat16* __restrict__ qh, const __nv_bfloat16* __restrict__ ql,
    const __nv_bfloat16* __restrict__ kh, const __nv_bfloat16* __restrict__ kl,
    const __nv_bfloat16* __restrict__ vh,
    const float* __restrict__ am,
    __nv_bfloat16* __restrict__ oh, __nv_bfloat16* __restrict__ ol)
{
    extern __shared__ char smem[];
    uint32_t sb = smem_u32(smem);
    float* maskf = (float*)(smem + FA_MB);

    int qt = blockIdx.x;              // 0..7
    int bh = blockIdx.y;              // 0..31
    int b  = bh >> 4, hd = bh & 15;
    int tid = threadIdx.x;
    int wid = tid >> 5, lane = tid & 31;
    int wm = wid * 16;
    int lrow  = lane & 15;
    int lcol8 = (lane >> 4) * 8;

    size_t qrow0 = (size_t)b * SS + qt * 128;
    size_t hoff  = (size_t)hd * DKK;

    // ---- load Q tile (hi, lo) + KV tile 0 (one group) ----
#pragma unroll
    for (int i = 0; i < 4; i++) {
        int id = i * 256 + tid;       // 0..1023
        int r = id >> 3, c = id & 7;
        uint32_t so = (uint32_t)(r * FA_STRIDE + c * 16);
        size_t gq = (qrow0 + r) * DD + hoff + c * 8;
        CP16(sb + FA_QH + so, (const char*)(qh + gq));
        CP16(sb + FA_QL + so, (const char*)(ql + gq));
        size_t gk = ((size_t)b * SS + r) * DD + hoff + c * 8;
        CP16(sb + FA_KV0 +         so, (const char*)(kh + gk));
        CP16(sb + FA_KV0 + 18432 + so, (const char*)(kl + gk));
        CP16(sb + FA_KV0 + 36864 + so, (const char*)(vh + gk));
    }
    CP_COMMIT();
    if (tid < 128) {
        float m = am[(size_t)b * SS + tid];
        maskf[tid] = (m == 0.f) ? -1e9f : 0.f;
    }

    float m0 = -1e30f, m1 = -1e30f, s0 = 0.f, s1 = 0.f;
    float oacc[8][4];
#pragma unroll
    for (int i = 0; i < 8; i++)
#pragma unroll
        for (int j = 0; j < 4; j++) oacc[i][j] = 0.f;

    for (int t = 0; t < 8; t++) {
        asm volatile("cp.async.wait_group 0;" ::: "memory");
        __syncthreads();

        // prefetch KV tile t+1 into the other buffer (overlaps compute below)
        if (t + 1 < 8) {
            uint32_t kvn = sb + FA_KV0 + (uint32_t)((t + 1) & 1) * FA_KVSTAGE;
#pragma unroll
            for (int i = 0; i < 4; i++) {
                int id = i * 256 + tid;
                int r = id >> 3, c = id & 7;
                uint32_t so = (uint32_t)(r * FA_STRIDE + c * 16);
                size_t go = ((size_t)b * SS + (t + 1) * 128 + r) * DD + hoff + c * 8;
                CP16(kvn +         so, (const char*)(kh + go));
                CP16(kvn + 18432 + so, (const char*)(kl + go));
                CP16(kvn + 36864 + so, (const char*)(vh + go));
            }
            CP_COMMIT();
            if (tid < 128) {
                float m = am[(size_t)b * SS + (t + 1) * 128 + tid];
                maskf[((t + 1) & 1) * 128 + tid] = (m == 0.f) ? -1e9f : 0.f;
            }
        }

        uint32_t kvb = sb + FA_KV0 + (uint32_t)(t & 1) * FA_KVSTAGE;
        const float* mk = maskf + (t & 1) * 128;

        // ---- scores: S[16][128] fp32 ----
        float sacc[16][4];
#pragma unroll
        for (int i = 0; i < 16; i++)
#pragma unroll
            for (int j = 0; j < 4; j++) sacc[i][j] = 0.f;

#pragma unroll
        for (int kf = 0; kf < 4; kf++) {
            uint32_t aqh[4], aql[4];
            uint32_t ad = sb + FA_QH + (uint32_t)((wm + lrow) * FA_STRIDE + (kf * 16 + lcol8) * 2);
            LDSM4(aqh, ad);
            LDSM4(aql, ad + (FA_QL - FA_QH));
#pragma unroll
            for (int nf2 = 0; nf2 < 8; nf2++) {
                uint32_t kd = kvb + (uint32_t)((nf2 * 16 + lrow) * FA_STRIDE + (kf * 16 + lcol8) * 2);
                uint32_t tmp[4];
                uint32_t bhf[2][2], blf[2][2];
                LDSM4(tmp, kd);
                bhf[0][0] = tmp[0]; bhf[0][1] = tmp[2];
                bhf[1][0] = tmp[1]; bhf[1][1] = tmp[3];
                LDSM4(tmp, kd + 18432);
                blf[0][0] = tmp[0]; blf[0][1] = tmp[2];
                blf[1][0] = tmp[1]; blf[1][1] = tmp[3];
#pragma unroll
                for (int u = 0; u < 2; u++) {
                    MMA16816(sacc[nf2*2+u], aqh, bhf[u]);
                    MMA16816(sacc[nf2*2+u], aqh, blf[u]);
                    MMA16816(sacc[nf2*2+u], aql, bhf[u]);
                }
            }
        }

        // ---- online softmax ----
        float mn0 = m0, mn1 = m1;
#pragma unroll
        for (int nf = 0; nf < 16; nf++) {
            int col = nf * 8 + (lane & 3) * 2;
            float b0 = mk[col], b1 = mk[col + 1];
            sacc[nf][0] = sacc[nf][0] * 0.125f + b0;
            sacc[nf][1] = sacc[nf][1] * 0.125f + b1;
            sacc[nf][2] = sacc[nf][2] * 0.125f + b0;
            sacc[nf][3] = sacc[nf][3] * 0.125f + b1;
            mn0 = fmaxf(mn0, fmaxf(sacc[nf][0], sacc[nf][1]));
            mn1 = fmaxf(mn1, fmaxf(sacc[nf][2], sacc[nf][3]));
        }
        mn0 = fmaxf(mn0, __shfl_xor_sync(0xffffffffu, mn0, 1));
        mn0 = fmaxf(mn0, __shfl_xor_sync(0xffffffffu, mn0, 2));
        mn1 = fmaxf(mn1, __shfl_xor_sync(0xffffffffu, mn1, 1));
        mn1 = fmaxf(mn1, __shfl_xor_sync(0xffffffffu, mn1, 2));
        float alpha0 = __expf(m0 - mn0);
        float alpha1 = __expf(m1 - mn1);
        m0 = mn0; m1 = mn1;
        float rs0 = 0.f, rs1 = 0.f;
#pragma unroll
        for (int nf = 0; nf < 16; nf++) {
            sacc[nf][0] = __expf(sacc[nf][0] - mn0);
            sacc[nf][1] = __expf(sacc[nf][1] - mn0);
            sacc[nf][2] = __expf(sacc[nf][2] - mn1);
            sacc[nf][3] = __expf(sacc[nf][3] - mn1);
            rs0 += sacc[nf][0] + sacc[nf][1];
            rs1 += sacc[nf][2] + sacc[nf][3];
        }
        rs0 += __shfl_xor_sync(0xffffffffu, rs0, 1);
        rs0 += __shfl_xor_sync(0xffffffffu, rs0, 2);
        rs1 += __shfl_xor_sync(0xffffffffu, rs1, 1);
        rs1 += __shfl_xor_sync(0xffffffffu, rs1, 2);
        s0 = s0 * alpha0 + rs0;
        s1 = s1 * alpha1 + rs1;
#pragma unroll
        for (int i = 0; i < 8; i++) {
            oacc[i][0] *= alpha0; oacc[i][1] *= alpha0;
            oacc[i][2] *= alpha1; oacc[i][3] *= alpha1;
        }

        // ---- O += P @ V ----
#pragma unroll
        for (int kk = 0; kk < 8; kk++) {
            uint32_t ap[4];
            ap[0] = bf2_hi(sacc[2*kk][0],   sacc[2*kk][1]);
            ap[1] = bf2_hi(sacc[2*kk][2],   sacc[2*kk][3]);
            ap[2] = bf2_hi(sacc[2*kk+1][0], sacc[2*kk+1][1]);
            ap[3] = bf2_hi(sacc[2*kk+1][2], sacc[2*kk+1][3]);
#pragma unroll
            for (int dv2 = 0; dv2 < 4; dv2++) {
                uint32_t tmp[4];
                uint32_t vd = kvb + 36864 + (uint32_t)((kk * 16 + lrow) * FA_STRIDE + (dv2 * 16 + lcol8) * 2);
                LDSM4T(tmp, vd);
                uint32_t bv0[2] = { tmp[0], tmp[1] };
                uint32_t bv1[2] = { tmp[2], tmp[3] };
                MMA16816(oacc[dv2*2],   ap, bv0);
                MMA16816(oacc[dv2*2+1], ap, bv1);
            }
        }
    }

    // ---- epilogue: O /= s, split store ----
    float inv0 = 1.0f / s0, inv1 = 1.0f / s1;
    int r0 = (int)qrow0 + wm + (lane >> 2);
#pragma unroll
    for (int nf = 0; nf < 8; nf++) {
        int col = (int)hoff + nf * 8 + (lane & 3) * 2;
        float a0 = oacc[nf][0] * inv0, a1 = oacc[nf][1] * inv0;
        float a2 = oacc[nf][2] * inv1, a3 = oacc[nf][3] * inv1;
        *(uint32_t*)&oh[(size_t)r0 * DD + col]       = bf2_hi(a0, a1);
        *(uint32_t*)&ol[(size_t)r0 * DD + col]       = bf2_lo(a0, a1);
        *(uint32_t*)&oh[(size_t)(r0 + 8) * DD + col] = bf2_hi(a2, a3);
        *(uint32_t*)&ol[(size_t)(r0 + 8) * DD + col] = bf2_lo(a2, a3);
    }
}

// ---------------- host orchestration ---------------------------------------------
extern "C" void kernel_launch(void* const* d_in, const int* in_sizes, int n_in,
                              void* d_out, int out_size)
{
    const int*   ids  = (const int*)  d_in[0];
    const float* am   = (const float*)d_in[1];
    const float* emb  = (const float*)d_in[2];
    const float* pe   = (const float*)d_in[3];
    const float* wq   = (const float*)d_in[4];
    const float* wk   = (const float*)d_in[5];
    const float* wv   = (const float*)d_in[6];
    const float* wo   = (const float*)d_in[7];
    const float* bo   = (const float*)d_in[8];
    const float* w1   = (const float*)d_in[9];
    const float* b1   = (const float*)d_in[10];
    const float* w2   = (const float*)d_in[11];
    const float* b2   = (const float*)d_in[12];
    const float* ln1s = (const float*)d_in[13];
    const float* ln1b = (const float*)d_in[14];
    const float* ln2s = (const float*)d_in[15];
    const float* ln2b = (const float*)d_in[16];
    const float* lnfs = (const float*)d_in[17];
    const float* lnfb = (const float*)d_in[18];
    float* out = (float*)d_out;

    float *x;
    __nv_bfloat16 *wh, *wl, *ah, *al, *fh, *fl, *qh_, *ql_, *kh_, *kl_, *vh_, *vl_;
    cudaGetSymbolAddress((void**)&x,   g_x);
    cudaGetSymbolAddress((void**)&wh,  g_wh);
    cudaGetSymbolAddress((void**)&wl,  g_wl);
    cudaGetSymbolAddress((void**)&ah,  g_ah);
    cudaGetSymbolAddress((void**)&al,  g_al);
    cudaGetSymbolAddress((void**)&fh,  g_fh);
    cudaGetSymbolAddress((void**)&fl,  g_fl);
    cudaGetSymbolAddress((void**)&qh_, g_qh);
    cudaGetSymbolAddress((void**)&ql_, g_ql);
    cudaGetSymbolAddress((void**)&kh_, g_kh);
    cudaGetSymbolAddress((void**)&kl_, g_kl);
    cudaGetSymbolAddress((void**)&vh_, g_vh);
    cudaGetSymbolAddress((void**)&vl_, g_vl);

    cudaFuncSetAttribute(mmagemm<3>, cudaFuncAttributeMaxDynamicSharedMemorySize, MM_SMEM);
    cudaFuncSetAttribute(mmagemm<4>, cudaFuncAttributeMaxDynamicSharedMemorySize, MM_SMEM);
    cudaFuncSetAttribute(mmagemm<5>, cudaFuncAttributeMaxDynamicSharedMemorySize, MM_SMEM);
    cudaFuncSetAttribute(flash_kernel, cudaFuncAttributeMaxDynamicSharedMemorySize, FA_SMEM);

    const int M = BB * SS;

    // batched weight prep: 3 launches
    prep_qkvo<<<dim3(DD/32, DD/32, 4*LL), 256>>>(wq, wk, wv, wo, wh, wl);
    prep_ff<<<dim3(FF_/32, DD/32, LL), 256>>>(w1, wh, wl, OFF_1, DD, FF_);
    prep_ff<<<dim3(DD/32, FF_/32, LL), 256>>>(w2, wh, wl, OFF_2, FF_, DD);

    embed_kernel<<<M, 256>>>(ids, emb, pe, x);

    for (int l = 0; l < LL; l++) {
        size_t lb = (size_t)l * WL_CHUNK;

        // LN1 -> split
        ln_split_kernel<<<M, 256>>>(x, ln1s + l*DD, ln1b + l*DD, ah, al);

        // fused Q,K,V projections -> split bf16
        BPtr pq = { wh + lb + OFF_Q, wl + lb + OFF_Q, nullptr, qh_, ql_ };
        BPtr pk = { wh + lb + OFF_K, wl + lb + OFF_K, nullptr, kh_, kl_ };
        BPtr pv = { wh + lb + OFF_V, wl + lb + OFF_V, nullptr, vh_, vl_ };
        mmagemm<4><<<dim3(DD/128, M/128, 3), 256, MM_SMEM>>>(ah, al, pq, pk, pv,
                                                             nullptr, nullptr, M, DD, DD);

        // flash attention -> split attn out in (ah, al)
        flash_kernel<<<dim3(SS/128, BB*HH), 256, FA_SMEM>>>(qh_, ql_, kh_, kl_, vh_,
                                                            am, ah, al);

        // x = x + attn @ Wo + bo
        BPtr po = { wh + lb + OFF_O, wl + lb + OFF_O, x, nullptr, nullptr };
        mmagemm<3><<<dim3(DD/128, M/128, 1), 256, MM_SMEM>>>(ah, al, po, po, po,
                                                             bo + l*DD, x, M, DD, DD);

        // LN2 -> split; ff = relu(h @ W1 + b1) -> split
        ln_split_kernel<<<M, 256>>>(x, ln2s + l*DD, ln2b + l*DD, ah, al);
        BPtr p1 = { wh + lb + OFF_1, wl + lb + OFF_1, nullptr, fh, fl };
        mmagemm<5><<<dim3(FF_/128, M/128, 1), 256, MM_SMEM>>>(ah, al, p1, p1, p1,
                                                              b1 + l*FF_, nullptr, M, FF_, DD);

        // x = x + ff @ W2 + b2
        BPtr p2 = { wh + lb + OFF_2, wl + lb + OFF_2, x, nullptr, nullptr };
        mmagemm<3><<<dim3(DD/128, M/128, 1), 256, MM_SMEM>>>(fh, fl, p2, p2, p2,
                                                             b2 + l*DD, x, M, DD, FF_);
    }

    ln_kernel<<<M, 256>>>(x, lnfs, lnfb, out);
}

// round 7
// speedup vs baseline: 3.1514x; 1.0687x over previous
#include <cuda_runtime.h>
#include <cuda_bf16.h>
#include <cstdint>

#define BB 2
#define SS 1024
#define DD 1024
#define HH 16
#define DKK 64
#define FF_ 4096
#define LL 6

// ---------------- scratch (__device__ globals: allocation-free) --------------
__device__ float g_x [BB*SS*DD];

// weights: per layer [Wq Wk Wv Wo W1 W2], each stored TRANSPOSED [N,K], split hi/lo
#define WL_CHUNK (4*DD*DD + DD*FF_ + FF_*DD)
#define W_TOTAL  (LL * WL_CHUNK)
#define OFF_Q 0
#define OFF_K (DD*DD)
#define OFF_V (2*DD*DD)
#define OFF_O (3*DD*DD)
#define OFF_1 (4*DD*DD)
#define OFF_2 (4*DD*DD + DD*FF_)
__device__ __nv_bfloat16 g_wh[W_TOTAL];
__device__ __nv_bfloat16 g_wl[W_TOTAL];

// split activations
__device__ __nv_bfloat16 g_ah[BB*SS*DD];
__device__ __nv_bfloat16 g_al[BB*SS*DD];
__device__ __nv_bfloat16 g_fh[BB*SS*FF_];
__device__ __nv_bfloat16 g_fl[BB*SS*FF_];
__device__ __nv_bfloat16 g_qh[BB*SS*DD];
__device__ __nv_bfloat16 g_ql[BB*SS*DD];
__device__ __nv_bfloat16 g_kh[BB*SS*DD];
__device__ __nv_bfloat16 g_kl[BB*SS*DD];
__device__ __nv_bfloat16 g_vh[BB*SS*DD];
__device__ __nv_bfloat16 g_vl[BB*SS*DD];

// ---------------- PTX helpers -------------------------------------------------
__device__ __forceinline__ uint32_t smem_u32(const void* p) {
    uint32_t a;
    asm("{ .reg .u64 t; cvta.to.shared.u64 t, %1; cvt.u32.u64 %0, t; }" : "=r"(a) : "l"(p));
    return a;
}
#define CP16(d, s) asm volatile("cp.async.cg.shared.global [%0], [%1], 16;" :: "r"(d), "l"(s))
#define CP_COMMIT() asm volatile("cp.async.commit_group;" ::: "memory")

#define LDSM4(r, addr) \
    asm volatile("ldmatrix.sync.aligned.m8n8.x4.shared.b16 {%0,%1,%2,%3}, [%4];" \
        : "=r"((r)[0]), "=r"((r)[1]), "=r"((r)[2]), "=r"((r)[3]) : "r"(addr))
#define LDSM4T(r, addr) \
    asm volatile("ldmatrix.sync.aligned.m8n8.x4.trans.shared.b16 {%0,%1,%2,%3}, [%4];" \
        : "=r"((r)[0]), "=r"((r)[1]), "=r"((r)[2]), "=r"((r)[3]) : "r"(addr))

#define MMA16816(d, a, b) \
    asm volatile("mma.sync.aligned.m16n8k16.row.col.f32.bf16.bf16.f32 " \
        "{%0,%1,%2,%3}, {%4,%5,%6,%7}, {%8,%9}, {%0,%1,%2,%3};" \
        : "+f"((d)[0]), "+f"((d)[1]), "+f"((d)[2]), "+f"((d)[3]) \
        : "r"((a)[0]), "r"((a)[1]), "r"((a)[2]), "r"((a)[3]), "r"((b)[0]), "r"((b)[1]))

__device__ __forceinline__ uint32_t bf2_hi(float a, float b) {
    __nv_bfloat16 ha = __float2bfloat16_rn(a), hb = __float2bfloat16_rn(b);
    return (uint32_t)__bfloat16_as_ushort(ha) | ((uint32_t)__bfloat16_as_ushort(hb) << 16);
}
__device__ __forceinline__ uint32_t bf2_lo(float a, float b) {
    __nv_bfloat16 ha = __float2bfloat16_rn(a), hb = __float2bfloat16_rn(b);
    __nv_bfloat16 la = __float2bfloat16_rn(a - __bfloat162float(ha));
    __nv_bfloat16 lb = __float2bfloat16_rn(b - __bfloat162float(hb));
    return (uint32_t)__bfloat16_as_ushort(la) | ((uint32_t)__bfloat16_as_ushort(lb) << 16);
}

// ---------------- block reductions --------------------------------------------
__device__ __forceinline__ float blockReduceSum(float v) {
    __shared__ float sh[8];
    __shared__ float res;
    int lane = threadIdx.x & 31, w = threadIdx.x >> 5;
#pragma unroll
    for (int o = 16; o; o >>= 1) v += __shfl_xor_sync(0xffffffffu, v, o);
    __syncthreads();
    if (lane == 0) sh[w] = v;
    __syncthreads();
    if (threadIdx.x == 0) {
        float s = 0.f;
#pragma unroll
        for (int i = 0; i < 8; i++) s += sh[i];
        res = s;
    }
    __syncthreads();
    return res;
}

// ---------------- embed --------------------------------------------------------
__global__ void __launch_bounds__(256) embed_kernel(
    const int* __restrict__ ids, const float* __restrict__ emb,
    const float* __restrict__ pe, float* __restrict__ x)
{
    int row = blockIdx.x;
    int col = threadIdx.x * 4;
    int id  = ids[row];
    int s   = row & (SS - 1);
    float4 e = *(const float4*)&emb[(size_t)id * DD + col];
    float4 p = *(const float4*)&pe [(size_t)s  * DD + col];
    float4 o;
    o.x = e.x * 32.0f + p.x;
    o.y = e.y * 32.0f + p.y;
    o.z = e.z * 32.0f + p.z;
    o.w = e.w * 32.0f + p.w;
    *(float4*)&x[(size_t)row * DD + col] = o;
}

// ---------------- LayerNorm: fp32 out (final) -----------------------------------
__global__ void __launch_bounds__(256) ln_kernel(
    const float* __restrict__ x, const float* __restrict__ g,
    const float* __restrict__ b, float* __restrict__ out)
{
    int row = blockIdx.x;
    int col = threadIdx.x * 4;
    float4 v = *(const float4*)&x[(size_t)row * DD + col];
    float mean = blockReduceSum(v.x + v.y + v.z + v.w) * (1.0f / DD);
    float dx = v.x - mean, dy = v.y - mean, dz = v.z - mean, dw = v.w - mean;
    float var = blockReduceSum(dx*dx + dy*dy + dz*dz + dw*dw) * (1.0f / DD);
    float rstd = rsqrtf(var + 1e-6f);
    float4 gg = *(const float4*)&g[col];
    float4 bb = *(const float4*)&b[col];
    float4 o;
    o.x = dx * rstd * gg.x + bb.x;
    o.y = dy * rstd * gg.y + bb.y;
    o.z = dz * rstd * gg.z + bb.z;
    o.w = dw * rstd * gg.w + bb.w;
    *(float4*)&out[(size_t)row * DD + col] = o;
}

// ---------------- LayerNorm: split bf16 hi/lo out --------------------------------
__global__ void __launch_bounds__(256) ln_split_kernel(
    const float* __restrict__ x, const float* __restrict__ g,
    const float* __restrict__ b, __nv_bfloat16* __restrict__ oh,
    __nv_bfloat16* __restrict__ ol)
{
    int row = blockIdx.x;
    int col = threadIdx.x * 4;
    float4 v = *(const float4*)&x[(size_t)row * DD + col];
    float mean = blockReduceSum(v.x + v.y + v.z + v.w) * (1.0f / DD);
    float dx = v.x - mean, dy = v.y - mean, dz = v.z - mean, dw = v.w - mean;
    float var = blockReduceSum(dx*dx + dy*dy + dz*dz + dw*dw) * (1.0f / DD);
    float rstd = rsqrtf(var + 1e-6f);
    float4 gg = *(const float4*)&g[col];
    float4 bb = *(const float4*)&b[col];
    float ox = dx * rstd * gg.x + bb.x;
    float oy = dy * rstd * gg.y + bb.y;
    float oz = dz * rstd * gg.z + bb.z;
    float ow = dw * rstd * gg.w + bb.w;
    size_t idx = ((size_t)row * DD + col) >> 2;
    uint2 H = make_uint2(bf2_hi(ox, oy), bf2_hi(oz, ow));
    uint2 L = make_uint2(bf2_lo(ox, oy), bf2_lo(oz, ow));
    ((uint2*)oh)[idx] = H;
    ((uint2*)ol)[idx] = L;
}

// ---------------- batched weight prep -------------------------------------------
__global__ void __launch_bounds__(256) prep_qkvo(
    const float* __restrict__ wq, const float* __restrict__ wk,
    const float* __restrict__ wv, const float* __restrict__ wo,
    __nv_bfloat16* __restrict__ dh, __nv_bfloat16* __restrict__ dl)
{
    __shared__ float tile[32][33];
    int z = blockIdx.z, l = z >> 2, ws = z & 3;
    const float* src = (ws == 0 ? wq : ws == 1 ? wk : ws == 2 ? wv : wo) + (size_t)l * DD * DD;
    size_t dbase = (size_t)l * WL_CHUNK + (size_t)ws * DD * DD;
    int k0 = blockIdx.y * 32, n0 = blockIdx.x * 32;
    int tx = threadIdx.x & 31, ty = threadIdx.x >> 5;
#pragma unroll
    for (int i = ty; i < 32; i += 8)
        tile[i][tx] = src[(size_t)(k0 + i) * DD + n0 + tx];
    __syncthreads();
#pragma unroll
    for (int i = ty; i < 32; i += 8) {
        float a = tile[tx][i];
        __nv_bfloat16 h = __float2bfloat16_rn(a);
        __nv_bfloat16 lo = __float2bfloat16_rn(a - __bfloat162float(h));
        size_t di = dbase + (size_t)(n0 + i) * DD + k0 + tx;
        dh[di] = h; dl[di] = lo;
    }
}

__global__ void __launch_bounds__(256) prep_ff(
    const float* __restrict__ src, __nv_bfloat16* __restrict__ dh,
    __nv_bfloat16* __restrict__ dl, int dstOff, int K, int N)
{
    __shared__ float tile[32][33];
    int l = blockIdx.z;
    const float* s = src + (size_t)l * K * N;
    size_t dbase = (size_t)l * WL_CHUNK + dstOff;
    int k0 = blockIdx.y * 32, n0 = blockIdx.x * 32;
    int tx = threadIdx.x & 31, ty = threadIdx.x >> 5;
#pragma unroll
    for (int i = ty; i < 32; i += 8)
        tile[i][tx] = s[(size_t)(k0 + i) * N + n0 + tx];
    __syncthreads();
#pragma unroll
    for (int i = ty; i < 32; i += 8) {
        float a = tile[tx][i];
        __nv_bfloat16 h = __float2bfloat16_rn(a);
        __nv_bfloat16 lo = __float2bfloat16_rn(a - __bfloat162float(h));
        size_t di = dbase + (size_t)(n0 + i) * K + k0 + tx;
        dh[di] = h; dl[di] = lo;
    }
}

// ================================================================================
// mma.sync split-bf16 GEMM: C[M,N] = A[M,K] @ Bt[N,K]^T  (3-term hi/lo)
// 2-stage cp.async pipeline, 80KB smem -> 2 CTAs/SM (latency hiding across CTAs).
// Inner loop consumes B fragments immediately to keep regs <= 128.
// EP: 3 = +bias+residual -> fp32 C      (Wo, FF2)
//     4 = split bf16 hi/lo out, no bias (QKV)
//     5 = relu(+bias), split bf16 out   (FF1)
// ================================================================================
struct BPtr {
    const __nv_bfloat16* h; const __nv_bfloat16* l;
    float* c; __nv_bfloat16* ch; __nv_bfloat16* cl;
};

#define STAGE_BYTES 40960
#define MM_SMEM (2 * STAGE_BYTES)

template<int EP>
__global__ void __launch_bounds__(256, 2) mmagemm(
    const __nv_bfloat16* __restrict__ Ah, const __nv_bfloat16* __restrict__ Al,
    BPtr p0, BPtr p1, BPtr p2,
    const float* __restrict__ bias, const float* __restrict__ Rs,
    int M, int N, int K)
{
    extern __shared__ char smem[];
    uint32_t sb = smem_u32(smem);
    int z = blockIdx.z;
    BPtr P = (z == 0) ? p0 : (z == 1 ? p1 : p2);
    const __nv_bfloat16* Bh = P.h;
    const __nv_bfloat16* Bl = P.l;

    int tid = threadIdx.x;
    int bm = blockIdx.y * 128, bn = blockIdx.x * 128;

    const __nv_bfloat16* Abh = Ah + (size_t)bm * K;
    const __nv_bfloat16* Abl = Al + (size_t)bm * K;
    const __nv_bfloat16* Bbh = Bh + (size_t)bn * K;
    const __nv_bfloat16* Bbl = Bl + (size_t)bn * K;

    auto load_stage = [&](int s, int k0) {
        uint32_t st = sb + s * STAGE_BYTES;
#pragma unroll
        for (int i = 0; i < 2; i++) {
            int id = i * 256 + tid;
            int r = id >> 2, c = id & 3;
            uint32_t so = (uint32_t)(r * 80 + c * 16);
            size_t go = (size_t)r * K + k0 + c * 8;
            CP16(st +         so, (const char*)(Abh + go));
            CP16(st + 10240 + so, (const char*)(Abl + go));
            CP16(st + 20480 + so, (const char*)(Bbh + go));
            CP16(st + 30720 + so, (const char*)(Bbl + go));
        }
    };

    int wid = tid >> 5, lane = tid & 31;
    int wm = (wid & 3) * 32;
    int wn = (wid >> 2) * 64;
    int lrow  = lane & 15;
    int lcol8 = (lane >> 4) * 8;

    float acc[2][8][4];
#pragma unroll
    for (int a = 0; a < 2; a++)
#pragma unroll
        for (int b = 0; b < 8; b++)
#pragma unroll
            for (int cth = 0; cth < 4; cth++) acc[a][b][cth] = 0.f;

    int NT = K >> 5;
    load_stage(0, 0);
    CP_COMMIT();

    for (int t = 0; t < NT; t++) {
        if (t + 1 < NT) {
            load_stage((t + 1) & 1, (t + 1) * 32);
            CP_COMMIT();
            asm volatile("cp.async.wait_group 1;" ::: "memory");
        } else {
            asm volatile("cp.async.wait_group 0;" ::: "memory");
        }
        __syncthreads();

        uint32_t sA = sb + (uint32_t)(t & 1) * STAGE_BYTES;
        uint32_t sB = sA + 20480;
#pragma unroll
        for (int ks = 0; ks < 2; ks++) {
            int k0 = ks * 16;
            uint32_t ah[2][4], al[2][4];
#pragma unroll
            for (int mf = 0; mf < 2; mf++) {
                uint32_t ad = sA + (uint32_t)((wm + mf * 16 + lrow) * 80 + (k0 + lcol8) * 2);
                LDSM4(ah[mf], ad);
                LDSM4(al[mf], ad + 10240);
            }
#pragma unroll
            for (int nf2 = 0; nf2 < 4; nf2++) {
                uint32_t ad = sB + (uint32_t)((wn + nf2 * 16 + lrow) * 80 + (k0 + lcol8) * 2);
                uint32_t tmp[4];
                uint32_t bh2[2][2], bl2[2][2];
                LDSM4(tmp, ad);
                bh2[0][0] = tmp[0]; bh2[0][1] = tmp[2];
                bh2[1][0] = tmp[1]; bh2[1][1] = tmp[3];
                LDSM4(tmp, ad + 10240);
                bl2[0][0] = tmp[0]; bl2[0][1] = tmp[2];
                bl2[1][0] = tmp[1]; bl2[1][1] = tmp[3];
#pragma unroll
                for (int u = 0; u < 2; u++) {
                    int nf = nf2 * 2 + u;
#pragma unroll
                    for (int mf = 0; mf < 2; mf++) {
                        MMA16816(acc[mf][nf], ah[mf], bh2[u]);
                        MMA16816(acc[mf][nf], ah[mf], bl2[u]);
                        MMA16816(acc[mf][nf], al[mf], bh2[u]);
                    }
                }
            }
        }
        __syncthreads();
    }

    // epilogue
#pragma unroll
    for (int mf = 0; mf < 2; mf++) {
        int r0 = bm + wm + mf * 16 + (lane >> 2);
#pragma unroll
        for (int nf = 0; nf < 8; nf++) {
            int col = bn + wn + nf * 8 + (lane & 3) * 2;
            float2 v0 = make_float2(acc[mf][nf][0], acc[mf][nf][1]);
            float2 v1 = make_float2(acc[mf][nf][2], acc[mf][nf][3]);
            if (EP == 3 || EP == 5) {
                float2 bi = *(const float2*)&bias[col];
                v0.x += bi.x; v0.y += bi.y; v1.x += bi.x; v1.y += bi.y;
            }
            if (EP == 5) {
                v0.x = fmaxf(v0.x, 0.f); v0.y = fmaxf(v0.y, 0.f);
                v1.x = fmaxf(v1.x, 0.f); v1.y = fmaxf(v1.y, 0.f);
            }
            if (EP == 3) {
                float2 r0v = *(const float2*)&Rs[(size_t)r0 * N + col];
                float2 r1v = *(const float2*)&Rs[(size_t)(r0 + 8) * N + col];
                v0.x += r0v.x; v0.y += r0v.y; v1.x += r1v.x; v1.y += r1v.y;
                *(float2*)&P.c[(size_t)r0 * N + col] = v0;
                *(float2*)&P.c[(size_t)(r0 + 8) * N + col] = v1;
            } else {
                *(uint32_t*)&P.ch[(size_t)r0 * N + col]       = bf2_hi(v0.x, v0.y);
                *(uint32_t*)&P.ch[(size_t)(r0 + 8) * N + col] = bf2_hi(v1.x, v1.y);
                *(uint32_t*)&P.cl[(size_t)r0 * N + col]       = bf2_lo(v0.x, v0.y);
                *(uint32_t*)&P.cl[(size_t)(r0 + 8) * N + col] = bf2_lo(v1.x, v1.y);
            }
        }
    }
}

// ================================================================================
// Flash attention: per (b,h) and 128-row Q tile. Online softmax, HMMA.
// Double-buffered KV tiles.
// ================================================================================
#define FA_STRIDE 144
#define FA_QH 0
#define FA_QL 18432
#define FA_KV0 36864
#define FA_KVSTAGE 55296      /* KH +0, KL +18432, V +36864 */
#define FA_MB 147456          /* 2 x 128 floats */
#define FA_SMEM 148480

__global__ void __launch_bounds__(256, 1) flash_kernel(
    const __nv_bfloat16* __restrict__ qh, const __nv_bfloat16* __restrict__ ql,
    const __nv_bfloat16* __restrict__ kh, const __nv_bfloat16* __restrict__ kl,
    const __nv_bfloat16* __restrict__ vh,
    const float* __restrict__ am,
    __nv_bfloat16* __restrict__ oh, __nv_bfloat16* __restrict__ ol)
{
    extern __shared__ char smem[];
    uint32_t sb = smem_u32(smem);
    float* maskf = (float*)(smem + FA_MB);

    int qt = blockIdx.x;              // 0..7
    int bh = blockIdx.y;              // 0..31
    int b  = bh >> 4, hd = bh & 15;
    int tid = threadIdx.x;
    int wid = tid >> 5, lane = tid & 31;
    int wm = wid * 16;
    int lrow  = lane & 15;
    int lcol8 = (lane >> 4) * 8;

    size_t qrow0 = (size_t)b * SS + qt * 128;
    size_t hoff  = (size_t)hd * DKK;

    // ---- load Q tile (hi, lo) + KV tile 0 (one group) ----
#pragma unroll
    for (int i = 0; i < 4; i++) {
        int id = i * 256 + tid;       // 0..1023
        int r = id >> 3, c = id & 7;
        uint32_t so = (uint32_t)(r * FA_STRIDE + c * 16);
        size_t gq = (qrow0 + r) * DD + hoff + c * 8;
        CP16(sb + FA_QH + so, (const char*)(qh + gq));
        CP16(sb + FA_QL + so, (const char*)(ql + gq));
        size_t gk = ((size_t)b * SS + r) * DD + hoff + c * 8;
        CP16(sb + FA_KV0 +         so, (const char*)(kh + gk));
        CP16(sb + FA_KV0 + 18432 + so, (const char*)(kl + gk));
        CP16(sb + FA_KV0 + 36864 + so, (const char*)(vh + gk));
    }
    CP_COMMIT();
    if (tid < 128) {
        float m = am[(size_t)b * SS + tid];
        maskf[tid] = (m == 0.f) ? -1e9f : 0.f;
    }

    float m0 = -1e30f, m1 = -1e30f, s0 = 0.f, s1 = 0.f;
    float oacc[8][4];
#pragma unroll
    for (int i = 0; i < 8; i++)
#pragma unroll
        for (int j = 0; j < 4; j++) oacc[i][j] = 0.f;

    for (int t = 0; t < 8; t++) {
        asm volatile("cp.async.wait_group 0;" ::: "memory");
        __syncthreads();

        // prefetch KV tile t+1 into the other buffer
        if (t + 1 < 8) {
            uint32_t kvn = sb + FA_KV0 + (uint32_t)((t + 1) & 1) * FA_KVSTAGE;
#pragma unroll
            for (int i = 0; i < 4; i++) {
                int id = i * 256 + tid;
                int r = id >> 3, c = id & 7;
                uint32_t so = (uint32_t)(r * FA_STRIDE + c * 16);
                size_t go = ((size_t)b * SS + (t + 1) * 128 + r) * DD + hoff + c * 8;
                CP16(kvn +         so, (const char*)(kh + go));
                CP16(kvn + 18432 + so, (const char*)(kl + go));
                CP16(kvn + 36864 + so, (const char*)(vh + go));
            }
            CP_COMMIT();
            if (tid < 128) {
                float m = am[(size_t)b * SS + (t + 1) * 128 + tid];
                maskf[((t + 1) & 1) * 128 + tid] = (m == 0.f) ? -1e9f : 0.f;
            }
        }

        uint32_t kvb = sb + FA_KV0 + (uint32_t)(t & 1) * FA_KVSTAGE;
        const float* mk = maskf + (t & 1) * 128;

        // ---- scores: S[16][128] fp32 ----
        float sacc[16][4];
#pragma unroll
        for (int i = 0; i < 16; i++)
#pragma unroll
            for (int j = 0; j < 4; j++) sacc[i][j] = 0.f;

#pragma unroll
        for (int kf = 0; kf < 4; kf++) {
            uint32_t aqh[4], aql[4];
            uint32_t ad = sb + FA_QH + (uint32_t)((wm + lrow) * FA_STRIDE + (kf * 16 + lcol8) * 2);
            LDSM4(aqh, ad);
            LDSM4(aql, ad + (FA_QL - FA_QH));
#pragma unroll
            for (int nf2 = 0; nf2 < 8; nf2++) {
                uint32_t kd = kvb + (uint32_t)((nf2 * 16 + lrow) * FA_STRIDE + (kf * 16 + lcol8) * 2);
                uint32_t tmp[4];
                uint32_t bhf[2][2], blf[2][2];
                LDSM4(tmp, kd);
                bhf[0][0] = tmp[0]; bhf[0][1] = tmp[2];
                bhf[1][0] = tmp[1]; bhf[1][1] = tmp[3];
                LDSM4(tmp, kd + 18432);
                blf[0][0] = tmp[0]; blf[0][1] = tmp[2];
                blf[1][0] = tmp[1]; blf[1][1] = tmp[3];
#pragma unroll
                for (int u = 0; u < 2; u++) {
                    MMA16816(sacc[nf2*2+u], aqh, bhf[u]);
                    MMA16816(sacc[nf2*2+u], aqh, blf[u]);
                    MMA16816(sacc[nf2*2+u], aql, bhf[u]);
                }
            }
        }

        // ---- online softmax ----
        float mn0 = m0, mn1 = m1;
#pragma unroll
        for (int nf = 0; nf < 16; nf++) {
            int col = nf * 8 + (lane & 3) * 2;
            float b0 = mk[col], b1 = mk[col + 1];
            sacc[nf][0] = sacc[nf][0] * 0.125f + b0;
            sacc[nf][1] = sacc[nf][1] * 0.125f + b1;
            sacc[nf][2] = sacc[nf][2] * 0.125f + b0;
            sacc[nf][3] = sacc[nf][3] * 0.125f + b1;
            mn0 = fmaxf(mn0, fmaxf(sacc[nf][0], sacc[nf][1]));
            mn1 = fmaxf(mn1, fmaxf(sacc[nf][2], sacc[nf][3]));
        }
        mn0 = fmaxf(mn0, __shfl_xor_sync(0xffffffffu, mn0, 1));
        mn0 = fmaxf(mn0, __shfl_xor_sync(0xffffffffu, mn0, 2));
        mn1 = fmaxf(mn1, __shfl_xor_sync(0xffffffffu, mn1, 1));
        mn1 = fmaxf(mn1, __shfl_xor_sync(0xffffffffu, mn1, 2));
        float alpha0 = __expf(m0 - mn0);
        float alpha1 = __expf(m1 - mn1);
        m0 = mn0; m1 = mn1;
        float rs0 = 0.f, rs1 = 0.f;
#pragma unroll
        for (int nf = 0; nf < 16; nf++) {
            sacc[nf][0] = __expf(sacc[nf][0] - mn0);
            sacc[nf][1] = __expf(sacc[nf][1] - mn0);
            sacc[nf][2] = __expf(sacc[nf][2] - mn1);
            sacc[nf][3] = __expf(sacc[nf][3] - mn1);
            rs0 += sacc[nf][0] + sacc[nf][1];
            rs1 += sacc[nf][2] + sacc[nf][3];
        }
        rs0 += __shfl_xor_sync(0xffffffffu, rs0, 1);
        rs0 += __shfl_xor_sync(0xffffffffu, rs0, 2);
        rs1 += __shfl_xor_sync(0xffffffffu, rs1, 1);
        rs1 += __shfl_xor_sync(0xffffffffu, rs1, 2);
        s0 = s0 * alpha0 + rs0;
        s1 = s1 * alpha1 + rs1;
#pragma unroll
        for (int i = 0; i < 8; i++) {
            oacc[i][0] *= alpha0; oacc[i][1] *= alpha0;
            oacc[i][2] *= alpha1; oacc[i][3] *= alpha1;
        }

        // ---- O += P @ V ----
#pragma unroll
        for (int kk = 0; kk < 8; kk++) {
            uint32_t ap[4];
            ap[0] = bf2_hi(sacc[2*kk][0],   sacc[2*kk][1]);
            ap[1] = bf2_hi(sacc[2*kk][2],   sacc[2*kk][3]);
            ap[2] = bf2_hi(sacc[2*kk+1][0], sacc[2*kk+1][1]);
            ap[3] = bf2_hi(sacc[2*kk+1][2], sacc[2*kk+1][3]);
#pragma unroll
            for (int dv2 = 0; dv2 < 4; dv2++) {
                uint32_t tmp[4];
                uint32_t vd = kvb + 36864 + (uint32_t)((kk * 16 + lrow) * FA_STRIDE + (dv2 * 16 + lcol8) * 2);
                LDSM4T(tmp, vd);
                uint32_t bv0[2] = { tmp[0], tmp[1] };
                uint32_t bv1[2] = { tmp[2], tmp[3] };
                MMA16816(oacc[dv2*2],   ap, bv0);
                MMA16816(oacc[dv2*2+1], ap, bv1);
            }
        }
    }

    // ---- epilogue: O /= s, split store ----
    float inv0 = 1.0f / s0, inv1 = 1.0f / s1;
    int r0 = (int)qrow0 + wm + (lane >> 2);
#pragma unroll
    for (int nf = 0; nf < 8; nf++) {
        int col = (int)hoff + nf * 8 + (lane & 3) * 2;
        float a0 = oacc[nf][0] * inv0, a1 = oacc[nf][1] * inv0;
        float a2 = oacc[nf][2] * inv1, a3 = oacc[nf][3] * inv1;
        *(uint32_t*)&oh[(size_t)r0 * DD + col]       = bf2_hi(a0, a1);
        *(uint32_t*)&ol[(size_t)r0 * DD + col]       = bf2_lo(a0, a1);
        *(uint32_t*)&oh[(size_t)(r0 + 8) * DD + col] = bf2_hi(a2, a3);
        *(uint32_t*)&ol[(size_t)(r0 + 8) * DD + col] = bf2_lo(a2, a3);
    }
}

// ---------------- host orchestration ---------------------------------------------
extern "C" void kernel_launch(void* const* d_in, const int* in_sizes, int n_in,
                              void* d_out, int out_size)
{
    const int*   ids  = (const int*)  d_in[0];
    const float* am   = (const float*)d_in[1];
    const float* emb  = (const float*)d_in[2];
    const float* pe   = (const float*)d_in[3];
    const float* wq   = (const float*)d_in[4];
    const float* wk   = (const float*)d_in[5];
    const float* wv   = (const float*)d_in[6];
    const float* wo   = (const float*)d_in[7];
    const float* bo   = (const float*)d_in[8];
    const float* w1   = (const float*)d_in[9];
    const float* b1   = (const float*)d_in[10];
    const float* w2   = (const float*)d_in[11];
    const float* b2   = (const float*)d_in[12];
    const float* ln1s = (const float*)d_in[13];
    const float* ln1b = (const float*)d_in[14];
    const float* ln2s = (const float*)d_in[15];
    const float* ln2b = (const float*)d_in[16];
    const float* lnfs = (const float*)d_in[17];
    const float* lnfb = (const float*)d_in[18];
    float* out = (float*)d_out;

    float *x;
    __nv_bfloat16 *wh, *wl, *ah, *al, *fh, *fl, *qh_, *ql_, *kh_, *kl_, *vh_, *vl_;
    cudaGetSymbolAddress((void**)&x,   g_x);
    cudaGetSymbolAddress((void**)&wh,  g_wh);
    cudaGetSymbolAddress((void**)&wl,  g_wl);
    cudaGetSymbolAddress((void**)&ah,  g_ah);
    cudaGetSymbolAddress((void**)&al,  g_al);
    cudaGetSymbolAddress((void**)&fh,  g_fh);
    cudaGetSymbolAddress((void**)&fl,  g_fl);
    cudaGetSymbolAddress((void**)&qh_, g_qh);
    cudaGetSymbolAddress((void**)&ql_, g_ql);
    cudaGetSymbolAddress((void**)&kh_, g_kh);
    cudaGetSymbolAddress((void**)&kl_, g_kl);
    cudaGetSymbolAddress((void**)&vh_, g_vh);
    cudaGetSymbolAddress((void**)&vl_, g_vl);

    cudaFuncSetAttribute(mmagemm<3>, cudaFuncAttributeMaxDynamicSharedMemorySize, MM_SMEM);
    cudaFuncSetAttribute(mmagemm<4>, cudaFuncAttributeMaxDynamicSharedMemorySize, MM_SMEM);
    cudaFuncSetAttribute(mmagemm<5>, cudaFuncAttributeMaxDynamicSharedMemorySize, MM_SMEM);
    cudaFuncSetAttribute(flash_kernel, cudaFuncAttributeMaxDynamicSharedMemorySize, FA_SMEM);

    const int M = BB * SS;

    // batched weight prep: 3 launches
    prep_qkvo<<<dim3(DD/32, DD/32, 4*LL), 256>>>(wq, wk, wv, wo, wh, wl);
    prep_ff<<<dim3(FF_/32, DD/32, LL), 256>>>(w1, wh, wl, OFF_1, DD, FF_);
    prep_ff<<<dim3(DD/32, FF_/32, LL), 256>>>(w2, wh, wl, OFF_2, FF_, DD);

    embed_kernel<<<M, 256>>>(ids, emb, pe, x);

    for (int l = 0; l < LL; l++) {
        size_t lb = (size_t)l * WL_CHUNK;

        // LN1 -> split
        ln_split_kernel<<<M, 256>>>(x, ln1s + l*DD, ln1b + l*DD, ah, al);

        // fused Q,K,V projections -> split bf16
        BPtr pq = { wh + lb + OFF_Q, wl + lb + OFF_Q, nullptr, qh_, ql_ };
        BPtr pk = { wh + lb + OFF_K, wl + lb + OFF_K, nullptr, kh_, kl_ };
        BPtr pv = { wh + lb + OFF_V, wl + lb + OFF_V, nullptr, vh_, vl_ };
        mmagemm<4><<<dim3(DD/128, M/128, 3), 256, MM_SMEM>>>(ah, al, pq, pk, pv,
                                                             nullptr, nullptr, M, DD, DD);

        // flash attention -> split attn out in (ah, al)
        flash_kernel<<<dim3(SS/128, BB*HH), 256, FA_SMEM>>>(qh_, ql_, kh_, kl_, vh_,
                                                            am, ah, al);

        // x = x + attn @ Wo + bo
        BPtr po = { wh + lb + OFF_O, wl + lb + OFF_O, x, nullptr, nullptr };
        mmagemm<3><<<dim3(DD/128, M/128, 1), 256, MM_SMEM>>>(ah, al, po, po, po,
                                                             bo + l*DD, x, M, DD, DD);

        // LN2 -> split; ff = relu(h @ W1 + b1) -> split
        ln_split_kernel<<<M, 256>>>(x, ln2s + l*DD, ln2b + l*DD, ah, al);
        BPtr p1 = { wh + lb + OFF_1, wl + lb + OFF_1, nullptr, fh, fl };
        mmagemm<5><<<dim3(FF_/128, M/128, 1), 256, MM_SMEM>>>(ah, al, p1, p1, p1,
                                                              b1 + l*FF_, nullptr, M, FF_, DD);

        // x = x + ff @ W2 + b2
        BPtr p2 = { wh + lb + OFF_2, wl + lb + OFF_2, x, nullptr, nullptr };
        mmagemm<3><<<dim3(DD/128, M/128, 1), 256, MM_SMEM>>>(fh, fl, p2, p2, p2,
                                                             b2 + l*DD, x, M, DD, FF_);
    }

    ln_kernel<<<M, 256>>>(x, lnfs, lnfb, out);
}

// round 8
// speedup vs baseline: 7.7962x; 2.4739x over previous
#include <cuda_runtime.h>
#include <cuda_fp16.h>
#include <cstdint>

#define BB 2
#define SS 1024
#define DD 1024
#define HH 16
#define DKK 64
#define FF_ 4096
#define LL 6

// ---------------- scratch (__device__ globals: allocation-free) --------------
__device__ float g_x [BB*SS*DD];

// weights: per layer [Wq Wk Wv Wo W1 W2], each stored TRANSPOSED [N,K], fp16
#define WL_CHUNK (4*DD*DD + DD*FF_ + FF_*DD)
#define W_TOTAL  (LL * WL_CHUNK)
#define OFF_Q 0
#define OFF_K (DD*DD)
#define OFF_V (2*DD*DD)
#define OFF_O (3*DD*DD)
#define OFF_1 (4*DD*DD)
#define OFF_2 (4*DD*DD + DD*FF_)
__device__ __half g_w [W_TOTAL];

// fp16 activations
__device__ __half g_a [BB*SS*DD];     // LN out / attn out
__device__ __half g_f [BB*SS*FF_];    // FF1 out
__device__ __half g_q [BB*SS*DD];
__device__ __half g_k [BB*SS*DD];
__device__ __half g_v [BB*SS*DD];

// ---------------- PTX helpers -------------------------------------------------
__device__ __forceinline__ uint32_t smem_u32(const void* p) {
    uint32_t a;
    asm("{ .reg .u64 t; cvta.to.shared.u64 t, %1; cvt.u32.u64 %0, t; }" : "=r"(a) : "l"(p));
    return a;
}
#define CP16(d, s) asm volatile("cp.async.cg.shared.global [%0], [%1], 16;" :: "r"(d), "l"(s))
#define CP_COMMIT() asm volatile("cp.async.commit_group;" ::: "memory")

#define LDSM4(r, addr) \
    asm volatile("ldmatrix.sync.aligned.m8n8.x4.shared.b16 {%0,%1,%2,%3}, [%4];" \
        : "=r"((r)[0]), "=r"((r)[1]), "=r"((r)[2]), "=r"((r)[3]) : "r"(addr))
#define LDSM4T(r, addr) \
    asm volatile("ldmatrix.sync.aligned.m8n8.x4.trans.shared.b16 {%0,%1,%2,%3}, [%4];" \
        : "=r"((r)[0]), "=r"((r)[1]), "=r"((r)[2]), "=r"((r)[3]) : "r"(addr))

#define MMAF16(d, a, b) \
    asm volatile("mma.sync.aligned.m16n8k16.row.col.f32.f16.f16.f32 " \
        "{%0,%1,%2,%3}, {%4,%5,%6,%7}, {%8,%9}, {%0,%1,%2,%3};" \
        : "+f"((d)[0]), "+f"((d)[1]), "+f"((d)[2]), "+f"((d)[3]) \
        : "r"((a)[0]), "r"((a)[1]), "r"((a)[2]), "r"((a)[3]), "r"((b)[0]), "r"((b)[1]))

__device__ __forceinline__ uint32_t h2pack(float a, float b) {
    __half2 h = __floats2half2_rn(a, b);
    return *(uint32_t*)&h;
}

// ---------------- block reduce -------------------------------------------------
__device__ __forceinline__ float blockReduceSum(float v) {
    __shared__ float sh[8];
    __shared__ float res;
    int lane = threadIdx.x & 31, w = threadIdx.x >> 5;
#pragma unroll
    for (int o = 16; o; o >>= 1) v += __shfl_xor_sync(0xffffffffu, v, o);
    __syncthreads();
    if (lane == 0) sh[w] = v;
    __syncthreads();
    if (threadIdx.x == 0) {
        float s = 0.f;
#pragma unroll
        for (int i = 0; i < 8; i++) s += sh[i];
        res = s;
    }
    __syncthreads();
    return res;
}

// ---------------- embed --------------------------------------------------------
__global__ void __launch_bounds__(256) embed_kernel(
    const int* __restrict__ ids, const float* __restrict__ emb,
    const float* __restrict__ pe, float* __restrict__ x)
{
    int row = blockIdx.x;
    int col = threadIdx.x * 4;
    int id  = ids[row];
    int s   = row & (SS - 1);
    float4 e = *(const float4*)&emb[(size_t)id * DD + col];
    float4 p = *(const float4*)&pe [(size_t)s  * DD + col];
    float4 o;
    o.x = e.x * 32.0f + p.x;
    o.y = e.y * 32.0f + p.y;
    o.z = e.z * 32.0f + p.z;
    o.w = e.w * 32.0f + p.w;
    *(float4*)&x[(size_t)row * DD + col] = o;
}

// ---------------- LayerNorm: fp32 out (final) -----------------------------------
__global__ void __launch_bounds__(256) ln_kernel(
    const float* __restrict__ x, const float* __restrict__ g,
    const float* __restrict__ b, float* __restrict__ out)
{
    int row = blockIdx.x;
    int col = threadIdx.x * 4;
    float4 v = *(const float4*)&x[(size_t)row * DD + col];
    float mean = blockReduceSum(v.x + v.y + v.z + v.w) * (1.0f / DD);
    float dx = v.x - mean, dy = v.y - mean, dz = v.z - mean, dw = v.w - mean;
    float var = blockReduceSum(dx*dx + dy*dy + dz*dz + dw*dw) * (1.0f / DD);
    float rstd = rsqrtf(var + 1e-6f);
    float4 gg = *(const float4*)&g[col];
    float4 bb = *(const float4*)&b[col];
    float4 o;
    o.x = dx * rstd * gg.x + bb.x;
    o.y = dy * rstd * gg.y + bb.y;
    o.z = dz * rstd * gg.z + bb.z;
    o.w = dw * rstd * gg.w + bb.w;
    *(float4*)&out[(size_t)row * DD + col] = o;
}

// ---------------- LayerNorm: fp16 out --------------------------------------------
__global__ void __launch_bounds__(256) ln_h_kernel(
    const float* __restrict__ x, const float* __restrict__ g,
    const float* __restrict__ b, __half* __restrict__ oh)
{
    int row = blockIdx.x;
    int col = threadIdx.x * 4;
    float4 v = *(const float4*)&x[(size_t)row * DD + col];
    float mean = blockReduceSum(v.x + v.y + v.z + v.w) * (1.0f / DD);
    float dx = v.x - mean, dy = v.y - mean, dz = v.z - mean, dw = v.w - mean;
    float var = blockReduceSum(dx*dx + dy*dy + dz*dz + dw*dw) * (1.0f / DD);
    float rstd = rsqrtf(var + 1e-6f);
    float4 gg = *(const float4*)&g[col];
    float4 bb = *(const float4*)&b[col];
    float ox = dx * rstd * gg.x + bb.x;
    float oy = dy * rstd * gg.y + bb.y;
    float oz = dz * rstd * gg.z + bb.z;
    float ow = dw * rstd * gg.w + bb.w;
    uint2 H = make_uint2(h2pack(ox, oy), h2pack(oz, ow));
    ((uint2*)oh)[((size_t)row * DD + col) >> 2] = H;
}

// ---------------- batched weight prep (fp32 [K,N] -> fp16 [N,K]) ------------------
__global__ void __launch_bounds__(256) prep_qkvo(
    const float* __restrict__ wq, const float* __restrict__ wk,
    const float* __restrict__ wv, const float* __restrict__ wo,
    __half* __restrict__ dh)
{
    __shared__ float tile[32][33];
    int z = blockIdx.z, l = z >> 2, ws = z & 3;
    const float* src = (ws == 0 ? wq : ws == 1 ? wk : ws == 2 ? wv : wo) + (size_t)l * DD * DD;
    size_t dbase = (size_t)l * WL_CHUNK + (size_t)ws * DD * DD;
    int k0 = blockIdx.y * 32, n0 = blockIdx.x * 32;
    int tx = threadIdx.x & 31, ty = threadIdx.x >> 5;
#pragma unroll
    for (int i = ty; i < 32; i += 8)
        tile[i][tx] = src[(size_t)(k0 + i) * DD + n0 + tx];
    __syncthreads();
#pragma unroll
    for (int i = ty; i < 32; i += 8)
        dh[dbase + (size_t)(n0 + i) * DD + k0 + tx] = __float2half_rn(tile[tx][i]);
}

__global__ void __launch_bounds__(256) prep_ff(
    const float* __restrict__ src, __half* __restrict__ dh,
    int dstOff, int K, int N)
{
    __shared__ float tile[32][33];
    int l = blockIdx.z;
    const float* s = src + (size_t)l * K * N;
    size_t dbase = (size_t)l * WL_CHUNK + dstOff;
    int k0 = blockIdx.y * 32, n0 = blockIdx.x * 32;
    int tx = threadIdx.x & 31, ty = threadIdx.x >> 5;
#pragma unroll
    for (int i = ty; i < 32; i += 8)
        tile[i][tx] = s[(size_t)(k0 + i) * N + n0 + tx];
    __syncthreads();
#pragma unroll
    for (int i = ty; i < 32; i += 8)
        dh[dbase + (size_t)(n0 + i) * K + k0 + tx] = __float2half_rn(tile[tx][i]);
}

// ================================================================================
// fp16 GEMM (single term): C[M,N] = A[M,K] @ Bt[N,K]^T, fp32 accum.
// CTA 128x128, K-chunk 64, 2-stage cp.async, 2 CTAs/SM.
// Stage: A 128x144B + B 128x144B = 36864 B.
// EP: 3 = +bias+residual -> fp32 C      (Wo, FF2)
//     4 = fp16 out, no bias             (QKV)
//     5 = relu(+bias), fp16 out         (FF1)
// ================================================================================
struct BPtr { const __half* h; float* c; __half* ch; };

#define STAGE_BYTES 36864
#define MM_SMEM (2 * STAGE_BYTES)

template<int EP>
__global__ void __launch_bounds__(256, 2) mmagemm(
    const __half* __restrict__ Ah,
    BPtr p0, BPtr p1, BPtr p2,
    const float* __restrict__ bias, const float* __restrict__ Rs,
    int M, int N, int K)
{
    extern __shared__ char smem[];
    uint32_t sb = smem_u32(smem);
    int z = blockIdx.z;
    BPtr P = (z == 0) ? p0 : (z == 1 ? p1 : p2);
    const __half* Bh = P.h;

    int tid = threadIdx.x;
    int bm = blockIdx.y * 128, bn = blockIdx.x * 128;

    const __half* Ab = Ah + (size_t)bm * K;
    const __half* Bb = Bh + (size_t)bn * K;

    auto load_stage = [&](int s, int k0) {
        uint32_t st = sb + s * STAGE_BYTES;
#pragma unroll
        for (int i = 0; i < 4; i++) {
            int id = i * 256 + tid;          // 0..1023
            int r = id >> 3, c = id & 7;
            uint32_t so = (uint32_t)(r * 144 + c * 16);
            size_t go = (size_t)r * K + k0 + c * 8;
            CP16(st +         so, (const char*)(Ab + go));
            CP16(st + 18432 + so, (const char*)(Bb + go));
        }
    };

    int wid = tid >> 5, lane = tid & 31;
    int wm = (wid & 3) * 32;
    int wn = (wid >> 2) * 64;
    int lrow  = lane & 15;
    int lcol8 = (lane >> 4) * 8;

    float acc[2][8][4];
#pragma unroll
    for (int a = 0; a < 2; a++)
#pragma unroll
        for (int b = 0; b < 8; b++)
#pragma unroll
            for (int cth = 0; cth < 4; cth++) acc[a][b][cth] = 0.f;

    int NT = K >> 6;                        // chunks of 64
    load_stage(0, 0);
    CP_COMMIT();

    for (int t = 0; t < NT; t++) {
        if (t + 1 < NT) {
            load_stage((t + 1) & 1, (t + 1) * 64);
            CP_COMMIT();
            asm volatile("cp.async.wait_group 1;" ::: "memory");
        } else {
            asm volatile("cp.async.wait_group 0;" ::: "memory");
        }
        __syncthreads();

        uint32_t sA = sb + (uint32_t)(t & 1) * STAGE_BYTES;
        uint32_t sB = sA + 18432;
#pragma unroll
        for (int ks = 0; ks < 4; ks++) {
            int k0 = ks * 16;
            uint32_t ah[2][4];
#pragma unroll
            for (int mf = 0; mf < 2; mf++) {
                uint32_t ad = sA + (uint32_t)((wm + mf * 16 + lrow) * 144 + (k0 + lcol8) * 2);
                LDSM4(ah[mf], ad);
            }
#pragma unroll
            for (int nf2 = 0; nf2 < 4; nf2++) {
                uint32_t ad = sB + (uint32_t)((wn + nf2 * 16 + lrow) * 144 + (k0 + lcol8) * 2);
                uint32_t tmp[4];
                LDSM4(tmp, ad);
                uint32_t b0[2] = { tmp[0], tmp[2] };
                uint32_t b1[2] = { tmp[1], tmp[3] };
#pragma unroll
                for (int mf = 0; mf < 2; mf++) {
                    MMAF16(acc[mf][nf2*2],   ah[mf], b0);
                    MMAF16(acc[mf][nf2*2+1], ah[mf], b1);
                }
            }
        }
        __syncthreads();
    }

    // epilogue
#pragma unroll
    for (int mf = 0; mf < 2; mf++) {
        int r0 = bm + wm + mf * 16 + (lane >> 2);
#pragma unroll
        for (int nf = 0; nf < 8; nf++) {
            int col = bn + wn + nf * 8 + (lane & 3) * 2;
            float2 v0 = make_float2(acc[mf][nf][0], acc[mf][nf][1]);
            float2 v1 = make_float2(acc[mf][nf][2], acc[mf][nf][3]);
            if (EP == 3 || EP == 5) {
                float2 bi = *(const float2*)&bias[col];
                v0.x += bi.x; v0.y += bi.y; v1.x += bi.x; v1.y += bi.y;
            }
            if (EP == 5) {
                v0.x = fmaxf(v0.x, 0.f); v0.y = fmaxf(v0.y, 0.f);
                v1.x = fmaxf(v1.x, 0.f); v1.y = fmaxf(v1.y, 0.f);
            }
            if (EP == 3) {
                float2 r0v = *(const float2*)&Rs[(size_t)r0 * N + col];
                float2 r1v = *(const float2*)&Rs[(size_t)(r0 + 8) * N + col];
                v0.x += r0v.x; v0.y += r0v.y; v1.x += r1v.x; v1.y += r1v.y;
                *(float2*)&P.c[(size_t)r0 * N + col] = v0;
                *(float2*)&P.c[(size_t)(r0 + 8) * N + col] = v1;
            } else {
                *(uint32_t*)&P.ch[(size_t)r0 * N + col]       = h2pack(v0.x, v0.y);
                *(uint32_t*)&P.ch[(size_t)(r0 + 8) * N + col] = h2pack(v1.x, v1.y);
            }
        }
    }
}

// ================================================================================
// Flash attention: fp16 Q/K/V, fp32 accum, online softmax. 2 CTAs/SM.
// smem: Q 18432 | KV stages 2x36864 (K +0, V +18432) | masks 1024
// ================================================================================
#define FA_STRIDE 144
#define FA_Q 0
#define FA_KV0 18432
#define FA_KVSTAGE 36864
#define FA_MB 92160
#define FA_SMEM 93184

__global__ void __launch_bounds__(256, 2) flash_kernel(
    const __half* __restrict__ q, const __half* __restrict__ k,
    const __half* __restrict__ v,
    const float* __restrict__ am,
    __half* __restrict__ o)
{
    extern __shared__ char smem[];
    uint32_t sb = smem_u32(smem);
    float* maskf = (float*)(smem + FA_MB);

    int qt = blockIdx.x;              // 0..7
    int bh = blockIdx.y;              // 0..31
    int b  = bh >> 4, hd = bh & 15;
    int tid = threadIdx.x;
    int wid = tid >> 5, lane = tid & 31;
    int wm = wid * 16;
    int lrow  = lane & 15;
    int lcol8 = (lane >> 4) * 8;

    size_t qrow0 = (size_t)b * SS + qt * 128;
    size_t hoff  = (size_t)hd * DKK;

    // ---- load Q tile + KV tile 0 ----
#pragma unroll
    for (int i = 0; i < 4; i++) {
        int id = i * 256 + tid;       // 0..1023
        int r = id >> 3, c = id & 7;
        uint32_t so = (uint32_t)(r * FA_STRIDE + c * 16);
        size_t gq = (qrow0 + r) * DD + hoff + c * 8;
        CP16(sb + FA_Q + so, (const char*)(q + gq));
        size_t gk = ((size_t)b * SS + r) * DD + hoff + c * 8;
        CP16(sb + FA_KV0 +         so, (const char*)(k + gk));
        CP16(sb + FA_KV0 + 18432 + so, (const char*)(v + gk));
    }
    CP_COMMIT();
    if (tid < 128) {
        float m = am[(size_t)b * SS + tid];
        maskf[tid] = (m == 0.f) ? -1e9f : 0.f;
    }

    float m0 = -1e30f, m1 = -1e30f, s0 = 0.f, s1 = 0.f;
    float oacc[8][4];
#pragma unroll
    for (int i = 0; i < 8; i++)
#pragma unroll
        for (int j = 0; j < 4; j++) oacc[i][j] = 0.f;

    for (int t = 0; t < 8; t++) {
        asm volatile("cp.async.wait_group 0;" ::: "memory");
        __syncthreads();

        // prefetch KV tile t+1
        if (t + 1 < 8) {
            uint32_t kvn = sb + FA_KV0 + (uint32_t)((t + 1) & 1) * FA_KVSTAGE;
#pragma unroll
            for (int i = 0; i < 4; i++) {
                int id = i * 256 + tid;
                int r = id >> 3, c = id & 7;
                uint32_t so = (uint32_t)(r * FA_STRIDE + c * 16);
                size_t go = ((size_t)b * SS + (t + 1) * 128 + r) * DD + hoff + c * 8;
                CP16(kvn +         so, (const char*)(k + go));
                CP16(kvn + 18432 + so, (const char*)(v + go));
            }
            CP_COMMIT();
            if (tid < 128) {
                float m = am[(size_t)b * SS + (t + 1) * 128 + tid];
                maskf[((t + 1) & 1) * 128 + tid] = (m == 0.f) ? -1e9f : 0.f;
            }
        }

        uint32_t kvb = sb + FA_KV0 + (uint32_t)(t & 1) * FA_KVSTAGE;
        const float* mk = maskf + (t & 1) * 128;

        // ---- scores ----
        float sacc[16][4];
#pragma unroll
        for (int i = 0; i < 16; i++)
#pragma unroll
            for (int j = 0; j < 4; j++) sacc[i][j] = 0.f;

#pragma unroll
        for (int kf = 0; kf < 4; kf++) {
            uint32_t aq[4];
            uint32_t ad = sb + FA_Q + (uint32_t)((wm + lrow) * FA_STRIDE + (kf * 16 + lcol8) * 2);
            LDSM4(aq, ad);
#pragma unroll
            for (int nf2 = 0; nf2 < 8; nf2++) {
                uint32_t kd = kvb + (uint32_t)((nf2 * 16 + lrow) * FA_STRIDE + (kf * 16 + lcol8) * 2);
                uint32_t tmp[4];
                LDSM4(tmp, kd);
                uint32_t b0[2] = { tmp[0], tmp[2] };
                uint32_t b1[2] = { tmp[1], tmp[3] };
                MMAF16(sacc[nf2*2],   aq, b0);
                MMAF16(sacc[nf2*2+1], aq, b1);
            }
        }

        // ---- online softmax ----
        float mn0 = m0, mn1 = m1;
#pragma unroll
        for (int nf = 0; nf < 16; nf++) {
            int col = nf * 8 + (lane & 3) * 2;
            float b0 = mk[col], b1 = mk[col + 1];
            sacc[nf][0] = sacc[nf][0] * 0.125f + b0;
            sacc[nf][1] = sacc[nf][1] * 0.125f + b1;
            sacc[nf][2] = sacc[nf][2] * 0.125f + b0;
            sacc[nf][3] = sacc[nf][3] * 0.125f + b1;
            mn0 = fmaxf(mn0, fmaxf(sacc[nf][0], sacc[nf][1]));
            mn1 = fmaxf(mn1, fmaxf(sacc[nf][2], sacc[nf][3]));
        }
        mn0 = fmaxf(mn0, __shfl_xor_sync(0xffffffffu, mn0, 1));
        mn0 = fmaxf(mn0, __shfl_xor_sync(0xffffffffu, mn0, 2));
        mn1 = fmaxf(mn1, __shfl_xor_sync(0xffffffffu, mn1, 1));
        mn1 = fmaxf(mn1, __shfl_xor_sync(0xffffffffu, mn1, 2));
        float alpha0 = __expf(m0 - mn0);
        float alpha1 = __expf(m1 - mn1);
        m0 = mn0; m1 = mn1;
        float rs0 = 0.f, rs1 = 0.f;
#pragma unroll
        for (int nf = 0; nf < 16; nf++) {
            sacc[nf][0] = __expf(sacc[nf][0] - mn0);
            sacc[nf][1] = __expf(sacc[nf][1] - mn0);
            sacc[nf][2] = __expf(sacc[nf][2] - mn1);
            sacc[nf][3] = __expf(sacc[nf][3] - mn1);
            rs0 += sacc[nf][0] + sacc[nf][1];
            rs1 += sacc[nf][2] + sacc[nf][3];
        }
        rs0 += __shfl_xor_sync(0xffffffffu, rs0, 1);
        rs0 += __shfl_xor_sync(0xffffffffu, rs0, 2);
        rs1 += __shfl_xor_sync(0xffffffffu, rs1, 1);
        rs1 += __shfl_xor_sync(0xffffffffu, rs1, 2);
        s0 = s0 * alpha0 + rs0;
        s1 = s1 * alpha1 + rs1;
#pragma unroll
        for (int i = 0; i < 8; i++) {
            oacc[i][0] *= alpha0; oacc[i][1] *= alpha0;
            oacc[i][2] *= alpha1; oacc[i][3] *= alpha1;
        }

        // ---- O += P @ V ----
#pragma unroll
        for (int kk = 0; kk < 8; kk++) {
            uint32_t ap[4];
            ap[0] = h2pack(sacc[2*kk][0],   sacc[2*kk][1]);
            ap[1] = h2pack(sacc[2*kk][2],   sacc[2*kk][3]);
            ap[2] = h2pack(sacc[2*kk+1][0], sacc[2*kk+1][1]);
            ap[3] = h2pack(sacc[2*kk+1][2], sacc[2*kk+1][3]);
#pragma unroll
            for (int dv2 = 0; dv2 < 4; dv2++) {
                uint32_t tmp[4];
                uint32_t vd = kvb + 18432 + (uint32_t)((kk * 16 + lrow) * FA_STRIDE + (dv2 * 16 + lcol8) * 2);
                LDSM4T(tmp, vd);
                uint32_t bv0[2] = { tmp[0], tmp[1] };
                uint32_t bv1[2] = { tmp[2], tmp[3] };
                MMAF16(oacc[dv2*2],   ap, bv0);
                MMAF16(oacc[dv2*2+1], ap, bv1);
            }
        }
    }

    // ---- epilogue ----
    float inv0 = 1.0f / s0, inv1 = 1.0f / s1;
    int r0 = (int)qrow0 + wm + (lane >> 2);
#pragma unroll
    for (int nf = 0; nf < 8; nf++) {
        int col = (int)hoff + nf * 8 + (lane & 3) * 2;
        *(uint32_t*)&o[(size_t)r0 * DD + col]       = h2pack(oacc[nf][0] * inv0, oacc[nf][1] * inv0);
        *(uint32_t*)&o[(size_t)(r0 + 8) * DD + col] = h2pack(oacc[nf][2] * inv1, oacc[nf][3] * inv1);
    }
}

// ---------------- host orchestration ---------------------------------------------
extern "C" void kernel_launch(void* const* d_in, const int* in_sizes, int n_in,
                              void* d_out, int out_size)
{
    const int*   ids  = (const int*)  d_in[0];
    const float* am   = (const float*)d_in[1];
    const float* emb  = (const float*)d_in[2];
    const float* pe   = (const float*)d_in[3];
    const float* wq   = (const float*)d_in[4];
    const float* wk   = (const float*)d_in[5];
    const float* wv   = (const float*)d_in[6];
    const float* wo   = (const float*)d_in[7];
    const float* bo   = (const float*)d_in[8];
    const float* w1   = (const float*)d_in[9];
    const float* b1   = (const float*)d_in[10];
    const float* w2   = (const float*)d_in[11];
    const float* b2   = (const float*)d_in[12];
    const float* ln1s = (const float*)d_in[13];
    const float* ln1b = (const float*)d_in[14];
    const float* ln2s = (const float*)d_in[15];
    const float* ln2b = (const float*)d_in[16];
    const float* lnfs = (const float*)d_in[17];
    const float* lnfb = (const float*)d_in[18];
    float* out = (float*)d_out;

    float *x;
    __half *w, *a, *f, *q_, *k_, *v_;
    cudaGetSymbolAddress((void**)&x,  g_x);
    cudaGetSymbolAddress((void**)&w,  g_w);
    cudaGetSymbolAddress((void**)&a,  g_a);
    cudaGetSymbolAddress((void**)&f,  g_f);
    cudaGetSymbolAddress((void**)&q_, g_q);
    cudaGetSymbolAddress((void**)&k_, g_k);
    cudaGetSymbolAddress((void**)&v_, g_v);

    cudaFuncSetAttribute(mmagemm<3>, cudaFuncAttributeMaxDynamicSharedMemorySize, MM_SMEM);
    cudaFuncSetAttribute(mmagemm<4>, cudaFuncAttributeMaxDynamicSharedMemorySize, MM_SMEM);
    cudaFuncSetAttribute(mmagemm<5>, cudaFuncAttributeMaxDynamicSharedMemorySize, MM_SMEM);
    cudaFuncSetAttribute(flash_kernel, cudaFuncAttributeMaxDynamicSharedMemorySize, FA_SMEM);

    const int M = BB * SS;

    // launch order puts mmagemm<4> at slot 4 for the ncu capture
    embed_kernel<<<M, 256>>>(ids, emb, pe, x);
    prep_qkvo<<<dim3(DD/32, DD/32, 4*LL), 256>>>(wq, wk, wv, wo, w);

    for (int l = 0; l < LL; l++) {
        size_t lb = (size_t)l * WL_CHUNK;

        // LN1 -> fp16
        ln_h_kernel<<<M, 256>>>(x, ln1s + l*DD, ln1b + l*DD, a);

        // fused Q,K,V projections
        BPtr pq = { w + lb + OFF_Q, nullptr, q_ };
        BPtr pk = { w + lb + OFF_K, nullptr, k_ };
        BPtr pv = { w + lb + OFF_V, nullptr, v_ };
        mmagemm<4><<<dim3(DD/128, M/128, 3), 256, MM_SMEM>>>(a, pq, pk, pv,
                                                             nullptr, nullptr, M, DD, DD);

        if (l == 0) {
            prep_ff<<<dim3(FF_/32, DD/32, LL), 256>>>(w1, w, OFF_1, DD, FF_);
            prep_ff<<<dim3(DD/32, FF_/32, LL), 256>>>(w2, w, OFF_2, FF_, DD);
        }

        // flash attention -> fp16 attn out in a
        flash_kernel<<<dim3(SS/128, BB*HH), 256, FA_SMEM>>>(q_, k_, v_, am, a);

        // x = x + attn @ Wo + bo
        BPtr po = { w + lb + OFF_O, x, nullptr };
        mmagemm<3><<<dim3(DD/128, M/128, 1), 256, MM_SMEM>>>(a, po, po, po,
                                                             bo + l*DD, x, M, DD, DD);

        // LN2 -> fp16; ff = relu(h @ W1 + b1) -> fp16
        ln_h_kernel<<<M, 256>>>(x, ln2s + l*DD, ln2b + l*DD, a);
        BPtr p1 = { w + lb + OFF_1, nullptr, f };
        mmagemm<5><<<dim3(FF_/128, M/128, 1), 256, MM_SMEM>>>(a, p1, p1, p1,
                                                              b1 + l*FF_, nullptr, M, FF_, DD);

        // x = x + ff @ W2 + b2
        BPtr p2 = { w + lb + OFF_2, x, nullptr };
        mmagemm<3><<<dim3(DD/128, M/128, 1), 256, MM_SMEM>>>(f, p2, p2, p2,
                                                             b2 + l*DD, x, M, DD, FF_);
    }

    ln_kernel<<<M, 256>>>(x, lnfs, lnfb, out);
}